// round 11
// baseline (speedup 1.0000x reference)
#include <cuda_runtime.h>
#include <cstdint>
#include <math.h>

#define B_  2
#define T_  2048
#define D_  1024
#define H_  16
#define DH  64

// ------------------------- scratch: hi/lo plane globals -------------------------
__device__ uint32_t g_qh[4096*512], g_ql[4096*512];
__device__ uint32_t g_kh[4096*512], g_kl[4096*512];
__device__ uint32_t g_vh[4096*512], g_vl[4096*512];
__device__ uint32_t g_Wqh[1024*512], g_Wql[1024*512];
__device__ uint32_t g_Wkh[1024*512], g_Wkl[1024*512];
__device__ uint32_t g_Wvh[1024*512], g_Wvl[1024*512];
__device__ uint32_t g_Woh[1024*512], g_Wol[1024*512];
__device__ uint2    g_Qpk[B_*H_*T_*32];
__device__ uint32_t g_Kh[B_*H_*T_*32], g_Kl[B_*H_*T_*32];
__device__ float    g_V [B_*H_*T_*DH];
__device__ uint32_t g_Vh[(size_t)B_*H_*DH*1024], g_Vl[(size_t)B_*H_*DH*1024];
__device__ uint32_t g_Ah[(size_t)4096*512], g_Al[(size_t)4096*512];
__device__ int      g_mask_any;

// ------------------------- helpers -------------------------
__device__ __forceinline__ uint32_t packbf(float x, float y) {
    uint32_t r; asm("cvt.rn.bf16x2.f32 %0, %1, %2;" : "=r"(r) : "f"(y), "f"(x)); return r;
}
__device__ __forceinline__ void split2(float x, float y, uint32_t& h, uint32_t& l) {
    h = packbf(x, y);
    float hx = __uint_as_float(h << 16);
    float hy = __uint_as_float(h & 0xFFFF0000u);
    l = packbf(x - hx, y - hy);
}
__device__ __forceinline__ void mma_bf16(float* d, const uint32_t* a, uint32_t b0, uint32_t b1) {
    asm volatile("mma.sync.aligned.m16n8k16.row.col.f32.bf16.bf16.f32 "
        "{%0,%1,%2,%3}, {%4,%5,%6,%7}, {%8,%9}, {%0,%1,%2,%3};"
        : "+f"(d[0]), "+f"(d[1]), "+f"(d[2]), "+f"(d[3])
        : "r"(a[0]), "r"(a[1]), "r"(a[2]), "r"(a[3]), "r"(b0), "r"(b1));
}
__device__ __forceinline__ void ldx4(uint32_t* r, uint32_t addr) {
    asm volatile("ldmatrix.sync.aligned.m8n8.x4.shared.b16 {%0,%1,%2,%3}, [%4];"
        : "=r"(r[0]), "=r"(r[1]), "=r"(r[2]), "=r"(r[3]) : "r"(addr));
}
__device__ __forceinline__ float ex2(float x) {
    float y; asm("ex2.approx.f32 %0, %1;" : "=f"(y) : "f"(x)); return y;
}
__device__ __forceinline__ uint32_t s2u(const void* p) {
    return (uint32_t)__cvta_generic_to_shared(p);
}
#define CP16(d, s) asm volatile("cp.async.cg.shared.global [%0], [%1], 16;" :: "r"(d), "l"(s))
#define CP_COMMIT  asm volatile("cp.async.commit_group;" ::: "memory")
#define CP_WAIT1   asm volatile("cp.async.wait_group 1;" ::: "memory")
#define CP_WAIT0   asm volatile("cp.async.wait_group 0;" ::: "memory")

// ------------------------- prep kernels -------------------------
__global__ void zero_flag() { g_mask_any = 0; }
__global__ __launch_bounds__(256) void mask_scan(const uint4* __restrict__ m, int n4)
{
    uint32_t acc = 0;
    for (int i = blockIdx.x * 256 + threadIdx.x; i < n4; i += gridDim.x * 256) {
        uint4 v = m[i];
        acc |= v.x | v.y | v.z | v.w;
    }
    acc |= __shfl_xor_sync(0xffffffff, acc, 16);
    acc |= __shfl_xor_sync(0xffffffff, acc, 8);
    acc |= __shfl_xor_sync(0xffffffff, acc, 4);
    acc |= __shfl_xor_sync(0xffffffff, acc, 2);
    acc |= __shfl_xor_sync(0xffffffff, acc, 1);
    if ((threadIdx.x & 31) == 0 && acc) atomicOr(&g_mask_any, 1);
}

__global__ __launch_bounds__(256) void pack_all(
    const float* q, const float* k, const float* v,
    const float* Wq, const float* Wk, const float* Wv, const float* Wo)
{
    const size_t NI = 4096 * 512, NW = 1024 * 512;
    size_t gid = (size_t)blockIdx.x * 256 + threadIdx.x;
    const size_t stride = (size_t)gridDim.x * 256;
    const size_t total = 3 * NI + 4 * NW;
    for (size_t i = gid; i < total; i += stride) {
        const float* src; uint32_t *dh, *dl; size_t off;
        if (i < NI)            { src = q;  dh = g_qh;  dl = g_ql;  off = i; }
        else if (i < 2*NI)     { src = k;  dh = g_kh;  dl = g_kl;  off = i - NI; }
        else if (i < 3*NI)     { src = v;  dh = g_vh;  dl = g_vl;  off = i - 2*NI; }
        else if (i < 3*NI+NW)  { src = Wq; dh = g_Wqh; dl = g_Wql; off = i - 3*NI; }
        else if (i < 3*NI+2*NW){ src = Wk; dh = g_Wkh; dl = g_Wkl; off = i - 3*NI - NW; }
        else if (i < 3*NI+3*NW){ src = Wv; dh = g_Wvh; dl = g_Wvl; off = i - 3*NI - 2*NW; }
        else                   { src = Wo; dh = g_Woh; dl = g_Wol; off = i - 3*NI - 3*NW; }
        float2 vv = ((const float2*)src)[off];
        uint32_t h, l; split2(vv.x, vv.y, h, l);
        dh[off] = h; dl[off] = l;
    }
}

__global__ __launch_bounds__(128) void v_pack()
{
    __shared__ float tile[64][65];
    const int tid = threadIdx.x;
    const int bh = blockIdx.y, kt = blockIdx.x * 64;
    const float* Vb = g_V + ((size_t)bh * 2048 + kt) * 64;
#pragma unroll
    for (int i = 0; i < 16; i++) {
        int idx = tid + i * 128;
        int r = idx >> 5, dp = idx & 31;
        float2 v = ((const float2*)Vb)[r * 32 + dp];
        tile[r][dp * 2] = v.x; tile[r][dp * 2 + 1] = v.y;
    }
    __syncthreads();
#pragma unroll
    for (int i = 0; i < 16; i++) {
        int idx = tid + i * 128;
        int d = idx >> 5, kp = idx & 31;
        uint32_t h, l; split2(tile[2 * kp][d], tile[2 * kp + 1][d], h, l);
        size_t o = ((size_t)bh * 64 + d) * 1024 + (kt >> 1) + kp;
        g_Vh[o] = h; g_Vl[o] = l;
    }
}

// ------------------------- GEMM mainloop: 4 warps, warp tile 64x64 -------------------------
#define GSTR 20
#define PLW  (128 * GSTR)
#define STW  (4 * PLW)

__device__ __forceinline__ void gemm_mainloop_pl(
    const uint32_t* __restrict__ Ah, const uint32_t* __restrict__ Al,
    const uint32_t* __restrict__ Bh, const uint32_t* __restrict__ Bl,
    int bm, int bn, uint32_t* sm, float acc[4][8][4],
    int wm, int wn, int lane, int tid)
{
    const uint32_t* gAh = Ah + (size_t)bm * 512;
    const uint32_t* gAl = Al + (size_t)bm * 512;
    const uint32_t* gBh = Bh + (size_t)bn * 512;
    const uint32_t* gBl = Bl + (size_t)bn * 512;
    const int pr = tid >> 2, pj = (tid & 3) * 4;   // rows pr, pr+32, pr+64, pr+96

#define GISSUE(it_) do { \
    uint32_t* st_ = sm + ((it_) & 1) * STW; \
    _Pragma("unroll") \
    for (int u_ = 0; u_ < 4; u_++) { \
        const int row_ = pr + u_ * 32; \
        const size_t go_ = (size_t)row_ * 512 + (it_) * 16 + pj; \
        const int so_ = row_ * GSTR + pj; \
        CP16(s2u(&st_[so_]),            &gAh[go_]); \
        CP16(s2u(&st_[PLW + so_]),      &gAl[go_]); \
        CP16(s2u(&st_[2*PLW + so_]),    &gBh[go_]); \
        CP16(s2u(&st_[3*PLW + so_]),    &gBl[go_]); \
    } } while(0)

    const uint32_t smb = s2u(sm);
    const int lrow = (lane & 7) + ((lane >> 3) & 1) * 8;
    const int lseg = (lane >> 4) * 16;

    GISSUE(0); CP_COMMIT;
    for (int it = 0; it < 32; ++it) {
        if (it < 31) { GISSUE(it + 1); CP_COMMIT; CP_WAIT1; }
        else CP_WAIT0;
        __syncthreads();
        const uint32_t stb = smb + ((it & 1) * STW) * 4;
#pragma unroll
        for (int c = 0; c < 2; ++c) {
            uint32_t ah[4][4], al[4][4];
#pragma unroll
            for (int mt = 0; mt < 4; ++mt) {
                uint32_t ra = stb + (uint32_t)((wm + mt * 16 + lrow) * GSTR) * 4 + c * 32 + lseg;
                ldx4(ah[mt], ra);
                ldx4(al[mt], ra + PLW * 4);
            }
#pragma unroll
            for (int p = 0; p < 4; ++p) {
                uint32_t bbh[4], bbl[4];
                uint32_t rb = stb + (uint32_t)(2 * PLW) * 4
                            + (uint32_t)((wn + p * 16 + lrow) * GSTR) * 4 + c * 32 + lseg;
                ldx4(bbh, rb);
                ldx4(bbl, rb + PLW * 4);
#pragma unroll
                for (int mt = 0; mt < 4; ++mt) {
                    mma_bf16(acc[mt][2*p],   ah[mt], bbh[0], bbh[2]);
                    mma_bf16(acc[mt][2*p+1], ah[mt], bbh[1], bbh[3]);
                    mma_bf16(acc[mt][2*p],   ah[mt], bbl[0], bbl[2]);
                    mma_bf16(acc[mt][2*p+1], ah[mt], bbl[1], bbl[3]);
                    mma_bf16(acc[mt][2*p],   al[mt], bbh[0], bbh[2]);
                    mma_bf16(acc[mt][2*p+1], al[mt], bbh[1], bbh[3]);
                }
            }
        }
        __syncthreads();
    }
#undef GISSUE
}

// ------------------------- fused QKV projection -------------------------
#define QSCALE 0.18033688f   // (1/8) * log2(e)
__global__ __launch_bounds__(128, 2) void gemm_qkv()
{
    extern __shared__ __align__(16) uint32_t smw[];
    const int which = blockIdx.x >> 3;
    const int bn = (blockIdx.x & 7) * 128;
    const int bm = blockIdx.y * 128;

    const uint32_t* Ah = which == 0 ? g_qh : which == 1 ? g_kh : g_vh;
    const uint32_t* Al = which == 0 ? g_ql : which == 1 ? g_kl : g_vl;
    const uint32_t* Bh = which == 0 ? g_Wqh : which == 1 ? g_Wkh : g_Wvh;
    const uint32_t* Bl = which == 0 ? g_Wql : which == 1 ? g_Wkl : g_Wvl;

    const int tid = threadIdx.x;
    const int wid = tid >> 5, lane = tid & 31;
    const int wm = (wid & 1) * 64, wn = (wid >> 1) * 64;
    const int lr = lane >> 2, lc = lane & 3;

    float acc[4][8][4];
#pragma unroll
    for (int mt = 0; mt < 4; mt++)
#pragma unroll
        for (int nt = 0; nt < 8; nt++)
#pragma unroll
            for (int i = 0; i < 4; i++) acc[mt][nt][i] = 0.f;

    gemm_mainloop_pl(Ah, Al, Bh, Bl, bm, bn, smw, acc, wm, wn, lane, tid);

    if (which == 0) {
#pragma unroll
        for (int mt = 0; mt < 4; ++mt)
#pragma unroll
            for (int nt = 0; nt < 8; ++nt) {
                const int row  = bm + wm + mt * 16 + lr;
                const int col0 = bn + wn + nt * 8 + lc * 2;
                const int hh = col0 >> 6, j = (col0 & 63) >> 1;
                const float* d = acc[mt][nt];
                uint32_t h, l;
                int b = row >> 11, t = row & 2047;
                split2(d[0] * QSCALE, d[1] * QSCALE, h, l);
                g_Qpk[((size_t)(b * 16 + hh) * 2048 + t) * 32 + j] = make_uint2(h, l);
                b = (row + 8) >> 11; t = (row + 8) & 2047;
                split2(d[2] * QSCALE, d[3] * QSCALE, h, l);
                g_Qpk[((size_t)(b * 16 + hh) * 2048 + t) * 32 + j] = make_uint2(h, l);
            }
    } else if (which == 1) {
#pragma unroll
        for (int mt = 0; mt < 4; ++mt)
#pragma unroll
            for (int nt = 0; nt < 8; ++nt) {
                const int row  = bm + wm + mt * 16 + lr;
                const int col0 = bn + wn + nt * 8 + lc * 2;
                const int hh = col0 >> 6, j = (col0 & 63) >> 1;
                const float* d = acc[mt][nt];
                uint32_t h, l;
                int b = row >> 11, t = row & 2047;
                size_t o = ((size_t)(b * 16 + hh) * 2048 + t) * 32 + j;
                split2(d[0], d[1], h, l);
                g_Kh[o] = h; g_Kl[o] = l;
                b = (row + 8) >> 11; t = (row + 8) & 2047;
                o = ((size_t)(b * 16 + hh) * 2048 + t) * 32 + j;
                split2(d[2], d[3], h, l);
                g_Kh[o] = h; g_Kl[o] = l;
            }
    } else {
#pragma unroll
        for (int mt = 0; mt < 4; ++mt)
#pragma unroll
            for (int nt = 0; nt < 8; ++nt) {
                const int row  = bm + wm + mt * 16 + lr;
                const int col0 = bn + wn + nt * 8 + lc * 2;
                const int hh = col0 >> 6, dd = col0 & 63;
                const float* d = acc[mt][nt];
                int b = row >> 11, t = row & 2047;
                *(float2*)(g_V + (((size_t)(b * 16 + hh) * 2048 + t) * 64 + dd)) = make_float2(d[0], d[1]);
                b = (row + 8) >> 11; t = (row + 8) & 2047;
                *(float2*)(g_V + (((size_t)(b * 16 + hh) * 2048 + t) * 64 + dd)) = make_float2(d[2], d[3]);
            }
    }
}

// ------------------------- output projection -------------------------
__global__ __launch_bounds__(128, 2) void gemm_oproj(float* __restrict__ C)
{
    extern __shared__ __align__(16) uint32_t smw[];
    const int bn = blockIdx.x * 128;
    const int bm = blockIdx.y * 128;
    const int tid = threadIdx.x;
    const int wid = tid >> 5, lane = tid & 31;
    const int wm = (wid & 1) * 64, wn = (wid >> 1) * 64;
    const int lr = lane >> 2, lc = lane & 3;

    float acc[4][8][4];
#pragma unroll
    for (int mt = 0; mt < 4; mt++)
#pragma unroll
        for (int nt = 0; nt < 8; nt++)
#pragma unroll
            for (int i = 0; i < 4; i++) acc[mt][nt][i] = 0.f;

    gemm_mainloop_pl(g_Ah, g_Al, g_Woh, g_Wol, bm, bn, smw, acc, wm, wn, lane, tid);

#pragma unroll
    for (int mt = 0; mt < 4; ++mt)
#pragma unroll
        for (int nt = 0; nt < 8; ++nt) {
            const int row  = bm + wm + mt * 16 + lr;
            const int col0 = bn + wn + nt * 8 + lc * 2;
            const float* d = acc[mt][nt];
            *(float2*)(C + (size_t)row * 1024 + col0)       = make_float2(d[0], d[1]);
            *(float2*)(C + (size_t)(row + 8) * 1024 + col0) = make_float2(d[2], d[3]);
        }
}

// ------------------------- flash attention (unchanged from R9 winner) -------------------------
#define KSTR 36
__global__ __launch_bounds__(128, 4) void flash_attn6(
    const unsigned char* __restrict__ mask)
{
    __shared__ __align__(16) uint32_t SKh[64*KSTR], SKl[64*KSTR], SVh[64*KSTR], SVl[64*KSTR];

    const int tid = threadIdx.x;
    const int w = tid >> 5, lane = tid & 31;
    const int lr = lane >> 2, lc = lane & 3;
    const int bh = blockIdx.y, b = bh >> 4, h = bh & 15;
    const int q0 = blockIdx.x * 64;
    const int t0 = q0 + w * 16;
    const bool anymask = (g_mask_any != 0);

    uint32_t qh[4][4], ql[4][4];
    {
        const uint2* q0p = g_Qpk + ((size_t)bh * 2048 + t0 + lr) * 32;
        const uint2* q1p = q0p + 8 * 32;
#pragma unroll
        for (int c = 0; c < 4; c++) {
            const int j = c * 8 + lc;
            uint2 u;
            u = q0p[j];     qh[c][0] = u.x; ql[c][0] = u.y;
            u = q1p[j];     qh[c][1] = u.x; ql[c][1] = u.y;
            u = q0p[j + 4]; qh[c][2] = u.x; ql[c][2] = u.y;
            u = q1p[j + 4]; qh[c][3] = u.x; ql[c][3] = u.y;
        }
    }

    float m0 = -1e30f, m1 = -1e30f, l0 = 0.f, l1 = 0.f;
    float o[8][4];
#pragma unroll
    for (int nt = 0; nt < 8; nt++)
#pragma unroll
        for (int i = 0; i < 4; i++) o[nt][i] = 0.f;

    const unsigned char* mrow0 = mask + ((size_t)b * 2048 + t0 + lr) * 2048;
    const unsigned char* mrow1 = mrow0 + 8 * 2048;

    const uint32_t skh = s2u(SKh), skl = s2u(SKl), svh = s2u(SVh), svl = s2u(SVl);
    const int lrow = (lane & 7) + ((lane >> 3) & 1) * 8;
    const int lseg = (lane >> 4) * 16;

    for (int kt = 0; kt < 2048; kt += 64) {
        __syncthreads();
        {
            const uint32_t* KH = g_Kh + ((size_t)bh * 2048 + kt) * 32;
            const uint32_t* KL = g_Kl + ((size_t)bh * 2048 + kt) * 32;
            const uint32_t* VH = g_Vh + (size_t)bh * 64 * 1024 + (kt >> 1);
            const uint32_t* VL = g_Vl + (size_t)bh * 64 * 1024 + (kt >> 1);
#pragma unroll
            for (int i = 0; i < 4; i++) {
                int idx = tid + i * 128;
                int r = idx >> 3, j4 = (idx & 7) * 4;
                *(uint4*)&SKh[r * KSTR + j4] = *(const uint4*)&KH[r * 32 + j4];
                *(uint4*)&SKl[r * KSTR + j4] = *(const uint4*)&KL[r * 32 + j4];
                *(uint4*)&SVh[r * KSTR + j4] = *(const uint4*)&VH[(size_t)r * 1024 + j4];
                *(uint4*)&SVl[r * KSTR + j4] = *(const uint4*)&VL[(size_t)r * 1024 + j4];
            }
        }
        __syncthreads();

        float s[8][4];
#pragma unroll
        for (int nt = 0; nt < 8; nt++)
#pragma unroll
            for (int i = 0; i < 4; i++) s[nt][i] = 0.f;
#pragma unroll
        for (int c = 0; c < 4; c++) {
#pragma unroll
            for (int p = 0; p < 4; p++) {
                uint32_t kbh[4], kbl[4];
                uint32_t ra = (uint32_t)((p * 16 + lrow) * KSTR) * 4 + c * 32 + lseg;
                ldx4(kbh, skh + ra);
                ldx4(kbl, skl + ra);
                mma_bf16(s[2*p],   qh[c], kbh[0], kbh[2]);
                mma_bf16(s[2*p+1], qh[c], kbh[1], kbh[3]);
                mma_bf16(s[2*p],   qh[c], kbl[0], kbl[2]);
                mma_bf16(s[2*p+1], qh[c], kbl[1], kbl[3]);
                mma_bf16(s[2*p],   ql[c], kbh[0], kbh[2]);
                mma_bf16(s[2*p+1], ql[c], kbh[1], kbh[3]);
            }
        }

        if (anymask) {
#pragma unroll
            for (int nt = 0; nt < 8; nt++) {
                const int cc = kt + nt * 8 + lc * 2;
                if (mrow0[cc])     s[nt][0] = -1e30f;
                if (mrow0[cc + 1]) s[nt][1] = -1e30f;
                if (mrow1[cc])     s[nt][2] = -1e30f;
                if (mrow1[cc + 1]) s[nt][3] = -1e30f;
            }
        }

        float tm0 = -1e30f, tm1 = -1e30f;
#pragma unroll
        for (int nt = 0; nt < 8; nt++) {
            tm0 = fmaxf(tm0, fmaxf(s[nt][0], s[nt][1]));
            tm1 = fmaxf(tm1, fmaxf(s[nt][2], s[nt][3]));
        }
        tm0 = fmaxf(tm0, __shfl_xor_sync(0xffffffff, tm0, 1));
        tm0 = fmaxf(tm0, __shfl_xor_sync(0xffffffff, tm0, 2));
        tm1 = fmaxf(tm1, __shfl_xor_sync(0xffffffff, tm1, 1));
        tm1 = fmaxf(tm1, __shfl_xor_sync(0xffffffff, tm1, 2));
        float mn0 = fmaxf(m0, tm0), mn1 = fmaxf(m1, tm1);
        float cr0 = ex2(m0 - mn0), cr1 = ex2(m1 - mn1);
        m0 = mn0; m1 = mn1;
        float ts0 = 0.f, ts1 = 0.f;
#pragma unroll
        for (int nt = 0; nt < 8; nt++) {
            s[nt][0] = ex2(s[nt][0] - mn0);
            s[nt][1] = ex2(s[nt][1] - mn0);
            s[nt][2] = ex2(s[nt][2] - mn1);
            s[nt][3] = ex2(s[nt][3] - mn1);
            ts0 += s[nt][0] + s[nt][1];
            ts1 += s[nt][2] + s[nt][3];
        }
        ts0 += __shfl_xor_sync(0xffffffff, ts0, 1);
        ts0 += __shfl_xor_sync(0xffffffff, ts0, 2);
        ts1 += __shfl_xor_sync(0xffffffff, ts1, 1);
        ts1 += __shfl_xor_sync(0xffffffff, ts1, 2);
        l0 = l0 * cr0 + ts0;
        l1 = l1 * cr1 + ts1;
#pragma unroll
        for (int nt = 0; nt < 8; nt++) {
            o[nt][0] *= cr0; o[nt][1] *= cr0;
            o[nt][2] *= cr1; o[nt][3] *= cr1;
        }

#pragma unroll
        for (int kc = 0; kc < 4; kc++) {
            uint32_t ph[4], pl[4];
            split2(s[2*kc][0],   s[2*kc][1],   ph[0], pl[0]);
            split2(s[2*kc][2],   s[2*kc][3],   ph[1], pl[1]);
            split2(s[2*kc+1][0], s[2*kc+1][1], ph[2], pl[2]);
            split2(s[2*kc+1][2], s[2*kc+1][3], ph[3], pl[3]);
#pragma unroll
            for (int p = 0; p < 4; p++) {
                uint32_t vbh[4], vbl[4];
                uint32_t ra = (uint32_t)((p * 16 + lrow) * KSTR) * 4 + kc * 32 + lseg;
                ldx4(vbh, svh + ra);
                ldx4(vbl, svl + ra);
                mma_bf16(o[2*p],   ph, vbh[0], vbh[2]);
                mma_bf16(o[2*p+1], ph, vbh[1], vbh[3]);
                mma_bf16(o[2*p],   ph, vbl[0], vbl[2]);
                mma_bf16(o[2*p+1], ph, vbl[1], vbl[3]);
                mma_bf16(o[2*p],   pl, vbh[0], vbh[2]);
                mma_bf16(o[2*p+1], pl, vbh[1], vbh[3]);
            }
        }
    }

    const float inv0 = 1.f / l0, inv1 = 1.f / l1;
    uint32_t* A0h = g_Ah + ((size_t)b * 2048 + t0 + lr) * 512 + h * 32;
    uint32_t* A0l = g_Al + ((size_t)b * 2048 + t0 + lr) * 512 + h * 32;
#pragma unroll
    for (int nt = 0; nt < 8; nt++) {
        const int j = nt * 4 + lc;
        uint32_t hh, ll;
        split2(o[nt][0] * inv0, o[nt][1] * inv0, hh, ll);
        A0h[j] = hh; A0l[j] = ll;
        split2(o[nt][2] * inv1, o[nt][3] * inv1, hh, ll);
        A0h[8 * 512 + j] = hh; A0l[8 * 512 + j] = ll;
    }
}

extern "C" void kernel_launch(void* const* d_in, const int* in_sizes, int n_in,
                              void* d_out, int out_size)
{
    const float* query = (const float*)d_in[0];
    const float* key   = (const float*)d_in[1];
    const float* value = (const float*)d_in[2];
    const unsigned char* mask = (const unsigned char*)d_in[3];
    const float* Wq = (const float*)d_in[4];
    const float* Wk = (const float*)d_in[5];
    const float* Wv = (const float*)d_in[6];
    const float* Wo = (const float*)d_in[7];

    const int SMEM_GEMM = 2 * STW * 4;   // 81920 B
    cudaFuncSetAttribute(gemm_qkv,   cudaFuncAttributeMaxDynamicSharedMemorySize, SMEM_GEMM);
    cudaFuncSetAttribute(gemm_oproj, cudaFuncAttributeMaxDynamicSharedMemorySize, SMEM_GEMM);

    zero_flag<<<1, 1>>>();
    mask_scan<<<256, 256>>>((const uint4*)mask, (B_ * T_ * T_) / 16);

    pack_all<<<2048, 256>>>(query, key, value, Wq, Wk, Wv, Wo);

    dim3 gq(24, 32);
    gemm_qkv<<<gq, 128, SMEM_GEMM>>>();

    dim3 gv(32, 32);
    v_pack<<<gv, 128>>>();

    dim3 ga(T_ / 64, B_ * H_);
    flash_attn6<<<ga, 128>>>(mask);

    dim3 go(8, 32);
    gemm_oproj<<<go, 128, SMEM_GEMM>>>((float*)d_out);
}

// round 12
// speedup vs baseline: 1.3489x; 1.3489x over previous
#include <cuda_runtime.h>
#include <cstdint>
#include <math.h>

#define B_  2
#define T_  2048
#define D_  1024
#define H_  16
#define DH  64

// ------------------------- scratch globals -------------------------
__device__ uint32_t g_qh[4096*512], g_ql[4096*512];
__device__ uint32_t g_kh[4096*512], g_kl[4096*512];
__device__ uint32_t g_vh[4096*512], g_vl[4096*512];
__device__ uint32_t g_Wqh[1024*512], g_Wql[1024*512];
__device__ uint32_t g_Wkh[1024*512], g_Wkl[1024*512];
__device__ uint32_t g_Wvh[1024*512], g_Wvl[1024*512];
__device__ uint32_t g_Woh[1024*512], g_Wol[1024*512];
__device__ uint32_t g_Qp[B_*H_*T_*32];                 // fp16x2 Q (scaled log2e/8)
__device__ uint32_t g_Kp[B_*H_*T_*32];                 // fp16x2 K
__device__ float    g_V [B_*H_*T_*DH];
__device__ uint32_t g_Vp[(size_t)B_*H_*DH*1024];       // fp16x2 V^T [bh][d][kp]
__device__ uint32_t g_Ah[(size_t)4096*512], g_Al[(size_t)4096*512];
__device__ int      g_mask_any;

// ------------------------- helpers -------------------------
__device__ __forceinline__ uint32_t packbf(float x, float y) {
    uint32_t r; asm("cvt.rn.bf16x2.f32 %0, %1, %2;" : "=r"(r) : "f"(y), "f"(x)); return r;
}
__device__ __forceinline__ uint32_t packh(float x, float y) {
    uint32_t r; asm("cvt.rn.f16x2.f32 %0, %1, %2;" : "=r"(r) : "f"(y), "f"(x)); return r;
}
__device__ __forceinline__ void split2(float x, float y, uint32_t& h, uint32_t& l) {
    h = packbf(x, y);
    float hx = __uint_as_float(h << 16);
    float hy = __uint_as_float(h & 0xFFFF0000u);
    l = packbf(x - hx, y - hy);
}
__device__ __forceinline__ void mma_bf16(float* d, const uint32_t* a, uint32_t b0, uint32_t b1) {
    asm volatile("mma.sync.aligned.m16n8k16.row.col.f32.bf16.bf16.f32 "
        "{%0,%1,%2,%3}, {%4,%5,%6,%7}, {%8,%9}, {%0,%1,%2,%3};"
        : "+f"(d[0]), "+f"(d[1]), "+f"(d[2]), "+f"(d[3])
        : "r"(a[0]), "r"(a[1]), "r"(a[2]), "r"(a[3]), "r"(b0), "r"(b1));
}
__device__ __forceinline__ void mma_f16(float* d, const uint32_t* a, uint32_t b0, uint32_t b1) {
    asm volatile("mma.sync.aligned.m16n8k16.row.col.f32.f16.f16.f32 "
        "{%0,%1,%2,%3}, {%4,%5,%6,%7}, {%8,%9}, {%0,%1,%2,%3};"
        : "+f"(d[0]), "+f"(d[1]), "+f"(d[2]), "+f"(d[3])
        : "r"(a[0]), "r"(a[1]), "r"(a[2]), "r"(a[3]), "r"(b0), "r"(b1));
}
__device__ __forceinline__ void ldx4(uint32_t* r, uint32_t addr) {
    asm volatile("ldmatrix.sync.aligned.m8n8.x4.shared.b16 {%0,%1,%2,%3}, [%4];"
        : "=r"(r[0]), "=r"(r[1]), "=r"(r[2]), "=r"(r[3]) : "r"(addr));
}
__device__ __forceinline__ float ex2(float x) {
    float y; asm("ex2.approx.f32 %0, %1;" : "=f"(y) : "f"(x)); return y;
}
__device__ __forceinline__ uint32_t s2u(const void* p) {
    return (uint32_t)__cvta_generic_to_shared(p);
}
#define CP16(d, s) asm volatile("cp.async.cg.shared.global [%0], [%1], 16;" :: "r"(d), "l"(s))
#define CP_COMMIT  asm volatile("cp.async.commit_group;" ::: "memory")
#define CP_WAIT1   asm volatile("cp.async.wait_group 1;" ::: "memory")
#define CP_WAIT0   asm volatile("cp.async.wait_group 0;" ::: "memory")

// ------------------------- prep kernels -------------------------
__global__ void zero_flag() { g_mask_any = 0; }
__global__ __launch_bounds__(256) void mask_scan(const uint4* __restrict__ m, int n4)
{
    uint32_t acc = 0;
    for (int i = blockIdx.x * 256 + threadIdx.x; i < n4; i += gridDim.x * 256) {
        uint4 v = m[i];
        acc |= v.x | v.y | v.z | v.w;
    }
    acc |= __shfl_xor_sync(0xffffffff, acc, 16);
    acc |= __shfl_xor_sync(0xffffffff, acc, 8);
    acc |= __shfl_xor_sync(0xffffffff, acc, 4);
    acc |= __shfl_xor_sync(0xffffffff, acc, 2);
    acc |= __shfl_xor_sync(0xffffffff, acc, 1);
    if ((threadIdx.x & 31) == 0 && acc) atomicOr(&g_mask_any, 1);
}

__global__ __launch_bounds__(256) void pack_all(
    const float* q, const float* k, const float* v,
    const float* Wq, const float* Wk, const float* Wv, const float* Wo)
{
    const size_t NI = 4096 * 512, NW = 1024 * 512;
    size_t gid = (size_t)blockIdx.x * 256 + threadIdx.x;
    const size_t stride = (size_t)gridDim.x * 256;
    const size_t total = 3 * NI + 4 * NW;
    for (size_t i = gid; i < total; i += stride) {
        const float* src; uint32_t *dh, *dl; size_t off;
        if (i < NI)            { src = q;  dh = g_qh;  dl = g_ql;  off = i; }
        else if (i < 2*NI)     { src = k;  dh = g_kh;  dl = g_kl;  off = i - NI; }
        else if (i < 3*NI)     { src = v;  dh = g_vh;  dl = g_vl;  off = i - 2*NI; }
        else if (i < 3*NI+NW)  { src = Wq; dh = g_Wqh; dl = g_Wql; off = i - 3*NI; }
        else if (i < 3*NI+2*NW){ src = Wk; dh = g_Wkh; dl = g_Wkl; off = i - 3*NI - NW; }
        else if (i < 3*NI+3*NW){ src = Wv; dh = g_Wvh; dl = g_Wvl; off = i - 3*NI - 2*NW; }
        else                   { src = Wo; dh = g_Woh; dl = g_Wol; off = i - 3*NI - 3*NW; }
        float2 vv = ((const float2*)src)[off];
        uint32_t h, l; split2(vv.x, vv.y, h, l);
        dh[off] = h; dl[off] = l;
    }
}

__global__ __launch_bounds__(128) void v_pack()
{
    __shared__ float tile[64][65];
    const int tid = threadIdx.x;
    const int bh = blockIdx.y, kt = blockIdx.x * 64;
    const float* Vb = g_V + ((size_t)bh * 2048 + kt) * 64;
#pragma unroll
    for (int i = 0; i < 16; i++) {
        int idx = tid + i * 128;
        int r = idx >> 5, dp = idx & 31;
        float2 v = ((const float2*)Vb)[r * 32 + dp];
        tile[r][dp * 2] = v.x; tile[r][dp * 2 + 1] = v.y;
    }
    __syncthreads();
#pragma unroll
    for (int i = 0; i < 16; i++) {
        int idx = tid + i * 128;
        int d = idx >> 5, kp = idx & 31;
        g_Vp[((size_t)bh * 64 + d) * 1024 + (kt >> 1) + kp] =
            packh(tile[2 * kp][d], tile[2 * kp + 1][d]);
    }
}

// ------------------------- GEMM mainloop (R9/R10 winner config) -------------------------
#define GSTR 20
#define PLW  (128 * GSTR)
#define STW  (4 * PLW)

__device__ __forceinline__ void gemm_mainloop_pl(
    const uint32_t* __restrict__ Ah, const uint32_t* __restrict__ Al,
    const uint32_t* __restrict__ Bh, const uint32_t* __restrict__ Bl,
    int bm, int bn, uint32_t* sm, float acc[4][4][4],
    int wm, int wn, int lane, int tid)
{
    const uint32_t* gAh = Ah + (size_t)bm * 512;
    const uint32_t* gAl = Al + (size_t)bm * 512;
    const uint32_t* gBh = Bh + (size_t)bn * 512;
    const uint32_t* gBl = Bl + (size_t)bn * 512;
    const int pr = tid >> 2, pj = (tid & 3) * 4;

#define GISSUE(it_) do { \
    uint32_t* st_ = sm + ((it_) & 1) * STW; \
    _Pragma("unroll") \
    for (int u_ = 0; u_ < 2; u_++) { \
        const int row_ = pr + u_ * 64; \
        const size_t go_ = (size_t)row_ * 512 + (it_) * 16 + pj; \
        const int so_ = row_ * GSTR + pj; \
        CP16(s2u(&st_[so_]),            &gAh[go_]); \
        CP16(s2u(&st_[PLW + so_]),      &gAl[go_]); \
        CP16(s2u(&st_[2*PLW + so_]),    &gBh[go_]); \
        CP16(s2u(&st_[3*PLW + so_]),    &gBl[go_]); \
    } } while(0)

    const uint32_t smb = s2u(sm);
    const int lrow = (lane & 7) + ((lane >> 3) & 1) * 8;
    const int lseg = (lane >> 4) * 16;

    GISSUE(0); CP_COMMIT;
    for (int it = 0; it < 32; ++it) {
        if (it < 31) { GISSUE(it + 1); CP_COMMIT; CP_WAIT1; }
        else CP_WAIT0;
        __syncthreads();
        const uint32_t stb = smb + ((it & 1) * STW) * 4;
#pragma unroll
        for (int c = 0; c < 2; ++c) {
            uint32_t ah[4][4], al[4][4];
#pragma unroll
            for (int mt = 0; mt < 4; ++mt) {
                uint32_t ra = stb + (uint32_t)((wm + mt * 16 + lrow) * GSTR) * 4 + c * 32 + lseg;
                ldx4(ah[mt], ra);
                ldx4(al[mt], ra + PLW * 4);
            }
#pragma unroll
            for (int p = 0; p < 2; ++p) {
                uint32_t bbh[4], bbl[4];
                uint32_t rb = stb + (uint32_t)(2 * PLW) * 4
                            + (uint32_t)((wn + p * 16 + lrow) * GSTR) * 4 + c * 32 + lseg;
                ldx4(bbh, rb);
                ldx4(bbl, rb + PLW * 4);
#pragma unroll
                for (int mt = 0; mt < 4; ++mt) {
                    mma_bf16(acc[mt][2*p],   ah[mt], bbh[0], bbh[2]);
                    mma_bf16(acc[mt][2*p+1], ah[mt], bbh[1], bbh[3]);
                }
#pragma unroll
                for (int mt = 0; mt < 4; ++mt) {
                    mma_bf16(acc[mt][2*p],   ah[mt], bbl[0], bbl[2]);
                    mma_bf16(acc[mt][2*p+1], ah[mt], bbl[1], bbl[3]);
                }
#pragma unroll
                for (int mt = 0; mt < 4; ++mt) {
                    mma_bf16(acc[mt][2*p],   al[mt], bbh[0], bbh[2]);
                    mma_bf16(acc[mt][2*p+1], al[mt], bbh[1], bbh[3]);
                }
            }
        }
        __syncthreads();
    }
#undef GISSUE
}

// ------------------------- fused QKV projection -------------------------
#define QSCALE 0.18033688f   // (1/8) * log2(e)
__global__ __launch_bounds__(256, 2) void gemm_qkv()
{
    extern __shared__ __align__(16) uint32_t smw[];
    const int which = blockIdx.x >> 3;
    const int bn = (blockIdx.x & 7) * 128;
    const int bm = blockIdx.y * 128;

    const uint32_t* Ah = which == 0 ? g_qh : which == 1 ? g_kh : g_vh;
    const uint32_t* Al = which == 0 ? g_ql : which == 1 ? g_kl : g_vl;
    const uint32_t* Bh = which == 0 ? g_Wqh : which == 1 ? g_Wkh : g_Wvh;
    const uint32_t* Bl = which == 0 ? g_Wql : which == 1 ? g_Wkl : g_Wvl;

    const int tid = threadIdx.x;
    const int wid = tid >> 5, lane = tid & 31;
    const int wm = (wid & 1) * 64, wn = (wid >> 1) * 32;
    const int lr = lane >> 2, lc = lane & 3;

    float acc[4][4][4];
#pragma unroll
    for (int mt = 0; mt < 4; mt++)
#pragma unroll
        for (int nt = 0; nt < 4; nt++)
#pragma unroll
            for (int i = 0; i < 4; i++) acc[mt][nt][i] = 0.f;

    gemm_mainloop_pl(Ah, Al, Bh, Bl, bm, bn, smw, acc, wm, wn, lane, tid);

    if (which == 0) {
#pragma unroll
        for (int mt = 0; mt < 4; ++mt)
#pragma unroll
            for (int nt = 0; nt < 4; ++nt) {
                const int row  = bm + wm + mt * 16 + lr;
                const int col0 = bn + wn + nt * 8 + lc * 2;
                const int hh = col0 >> 6, j = (col0 & 63) >> 1;
                const float* d = acc[mt][nt];
                int b = row >> 11, t = row & 2047;
                g_Qp[((size_t)(b * 16 + hh) * 2048 + t) * 32 + j] =
                    packh(d[0] * QSCALE, d[1] * QSCALE);
                b = (row + 8) >> 11; t = (row + 8) & 2047;
                g_Qp[((size_t)(b * 16 + hh) * 2048 + t) * 32 + j] =
                    packh(d[2] * QSCALE, d[3] * QSCALE);
            }
    } else if (which == 1) {
#pragma unroll
        for (int mt = 0; mt < 4; ++mt)
#pragma unroll
            for (int nt = 0; nt < 4; ++nt) {
                const int row  = bm + wm + mt * 16 + lr;
                const int col0 = bn + wn + nt * 8 + lc * 2;
                const int hh = col0 >> 6, j = (col0 & 63) >> 1;
                const float* d = acc[mt][nt];
                int b = row >> 11, t = row & 2047;
                g_Kp[((size_t)(b * 16 + hh) * 2048 + t) * 32 + j] = packh(d[0], d[1]);
                b = (row + 8) >> 11; t = (row + 8) & 2047;
                g_Kp[((size_t)(b * 16 + hh) * 2048 + t) * 32 + j] = packh(d[2], d[3]);
            }
    } else {
#pragma unroll
        for (int mt = 0; mt < 4; ++mt)
#pragma unroll
            for (int nt = 0; nt < 4; ++nt) {
                const int row  = bm + wm + mt * 16 + lr;
                const int col0 = bn + wn + nt * 8 + lc * 2;
                const int hh = col0 >> 6, dd = col0 & 63;
                const float* d = acc[mt][nt];
                int b = row >> 11, t = row & 2047;
                *(float2*)(g_V + (((size_t)(b * 16 + hh) * 2048 + t) * 64 + dd)) = make_float2(d[0], d[1]);
                b = (row + 8) >> 11; t = (row + 8) & 2047;
                *(float2*)(g_V + (((size_t)(b * 16 + hh) * 2048 + t) * 64 + dd)) = make_float2(d[2], d[3]);
            }
    }
}

// ------------------------- output projection -------------------------
__global__ __launch_bounds__(256, 2) void gemm_oproj(float* __restrict__ C)
{
    extern __shared__ __align__(16) uint32_t smw[];
    const int bn = blockIdx.x * 128;
    const int bm = blockIdx.y * 128;
    const int tid = threadIdx.x;
    const int wid = tid >> 5, lane = tid & 31;
    const int wm = (wid & 1) * 64, wn = (wid >> 1) * 32;
    const int lr = lane >> 2, lc = lane & 3;

    float acc[4][4][4];
#pragma unroll
    for (int mt = 0; mt < 4; mt++)
#pragma unroll
        for (int nt = 0; nt < 4; nt++)
#pragma unroll
            for (int i = 0; i < 4; i++) acc[mt][nt][i] = 0.f;

    gemm_mainloop_pl(g_Ah, g_Al, g_Woh, g_Wol, bm, bn, smw, acc, wm, wn, lane, tid);

#pragma unroll
    for (int mt = 0; mt < 4; ++mt)
#pragma unroll
        for (int nt = 0; nt < 4; ++nt) {
            const int row  = bm + wm + mt * 16 + lr;
            const int col0 = bn + wn + nt * 8 + lc * 2;
            const float* d = acc[mt][nt];
            *(float2*)(C + (size_t)row * 1024 + col0)       = make_float2(d[0], d[1]);
            *(float2*)(C + (size_t)(row + 8) * 1024 + col0) = make_float2(d[2], d[3]);
        }
}

// ------------------------- flash attention: fp16 single-term -------------------------
#define KSTR 36
__global__ __launch_bounds__(128, 4) void flash_attn7(
    const unsigned char* __restrict__ mask)
{
    __shared__ __align__(16) uint32_t SK[64*KSTR], SV[64*KSTR];

    const int tid = threadIdx.x;
    const int w = tid >> 5, lane = tid & 31;
    const int lr = lane >> 2, lc = lane & 3;
    const int bh = blockIdx.y, b = bh >> 4, h = bh & 15;
    const int q0 = blockIdx.x * 64;
    const int t0 = q0 + w * 16;
    const bool anymask = (g_mask_any != 0);

    uint32_t qf[4][4];
    {
        const uint32_t* q0p = g_Qp + ((size_t)bh * 2048 + t0 + lr) * 32;
        const uint32_t* q1p = q0p + 8 * 32;
#pragma unroll
        for (int c = 0; c < 4; c++) {
            const int j = c * 8 + lc;
            qf[c][0] = q0p[j];     qf[c][1] = q1p[j];
            qf[c][2] = q0p[j + 4]; qf[c][3] = q1p[j + 4];
        }
    }

    float m0 = -1e30f, m1 = -1e30f, l0 = 0.f, l1 = 0.f;
    float o[8][4];
#pragma unroll
    for (int nt = 0; nt < 8; nt++)
#pragma unroll
        for (int i = 0; i < 4; i++) o[nt][i] = 0.f;

    const unsigned char* mrow0 = mask + ((size_t)b * 2048 + t0 + lr) * 2048;
    const unsigned char* mrow1 = mrow0 + 8 * 2048;

    const uint32_t sk = s2u(SK), sv = s2u(SV);
    const int lrow = (lane & 7) + ((lane >> 3) & 1) * 8;
    const int lseg = (lane >> 4) * 16;

    for (int kt = 0; kt < 2048; kt += 64) {
        __syncthreads();
        {
            const uint32_t* KP = g_Kp + ((size_t)bh * 2048 + kt) * 32;
            const uint32_t* VP = g_Vp + (size_t)bh * 64 * 1024 + (kt >> 1);
#pragma unroll
            for (int i = 0; i < 4; i++) {
                int idx = tid + i * 128;
                int r = idx >> 3, j4 = (idx & 7) * 4;
                *(uint4*)&SK[r * KSTR + j4] = *(const uint4*)&KP[r * 32 + j4];
                *(uint4*)&SV[r * KSTR + j4] = *(const uint4*)&VP[(size_t)r * 1024 + j4];
            }
        }
        __syncthreads();

        // S = Q K^T (fp16 single-term)
        float s[8][4];
#pragma unroll
        for (int nt = 0; nt < 8; nt++)
#pragma unroll
            for (int i = 0; i < 4; i++) s[nt][i] = 0.f;
#pragma unroll
        for (int c = 0; c < 4; c++) {
#pragma unroll
            for (int p = 0; p < 4; p++) {
                uint32_t kb[4];
                uint32_t ra = (uint32_t)((p * 16 + lrow) * KSTR) * 4 + c * 32 + lseg;
                ldx4(kb, sk + ra);
                mma_f16(s[2*p],   qf[c], kb[0], kb[2]);
                mma_f16(s[2*p+1], qf[c], kb[1], kb[3]);
            }
        }

        if (anymask) {
#pragma unroll
            for (int nt = 0; nt < 8; nt++) {
                const int cc = kt + nt * 8 + lc * 2;
                if (mrow0[cc])     s[nt][0] = -1e30f;
                if (mrow0[cc + 1]) s[nt][1] = -1e30f;
                if (mrow1[cc])     s[nt][2] = -1e30f;
                if (mrow1[cc + 1]) s[nt][3] = -1e30f;
            }
        }

        float tm0 = -1e30f, tm1 = -1e30f;
#pragma unroll
        for (int nt = 0; nt < 8; nt++) {
            tm0 = fmaxf(tm0, fmaxf(s[nt][0], s[nt][1]));
            tm1 = fmaxf(tm1, fmaxf(s[nt][2], s[nt][3]));
        }
        tm0 = fmaxf(tm0, __shfl_xor_sync(0xffffffff, tm0, 1));
        tm0 = fmaxf(tm0, __shfl_xor_sync(0xffffffff, tm0, 2));
        tm1 = fmaxf(tm1, __shfl_xor_sync(0xffffffff, tm1, 1));
        tm1 = fmaxf(tm1, __shfl_xor_sync(0xffffffff, tm1, 2));
        float mn0 = fmaxf(m0, tm0), mn1 = fmaxf(m1, tm1);
        float cr0 = ex2(m0 - mn0), cr1 = ex2(m1 - mn1);
        m0 = mn0; m1 = mn1;
        float ts0 = 0.f, ts1 = 0.f;
#pragma unroll
        for (int nt = 0; nt < 8; nt++) {
            s[nt][0] = ex2(s[nt][0] - mn0);
            s[nt][1] = ex2(s[nt][1] - mn0);
            s[nt][2] = ex2(s[nt][2] - mn1);
            s[nt][3] = ex2(s[nt][3] - mn1);
            ts0 += s[nt][0] + s[nt][1];
            ts1 += s[nt][2] + s[nt][3];
        }
        ts0 += __shfl_xor_sync(0xffffffff, ts0, 1);
        ts0 += __shfl_xor_sync(0xffffffff, ts0, 2);
        ts1 += __shfl_xor_sync(0xffffffff, ts1, 1);
        ts1 += __shfl_xor_sync(0xffffffff, ts1, 2);
        l0 = l0 * cr0 + ts0;
        l1 = l1 * cr1 + ts1;
#pragma unroll
        for (int nt = 0; nt < 8; nt++) {
            o[nt][0] *= cr0; o[nt][1] *= cr0;
            o[nt][2] *= cr1; o[nt][3] *= cr1;
        }

        // PV (fp16 single-term; P packed to fp16)
#pragma unroll
        for (int kc = 0; kc < 4; kc++) {
            uint32_t pf[4];
            pf[0] = packh(s[2*kc][0],   s[2*kc][1]);
            pf[1] = packh(s[2*kc][2],   s[2*kc][3]);
            pf[2] = packh(s[2*kc+1][0], s[2*kc+1][1]);
            pf[3] = packh(s[2*kc+1][2], s[2*kc+1][3]);
#pragma unroll
            for (int p = 0; p < 4; p++) {
                uint32_t vb[4];
                uint32_t ra = (uint32_t)((p * 16 + lrow) * KSTR) * 4 + kc * 32 + lseg;
                ldx4(vb, sv + ra);
                mma_f16(o[2*p],   pf, vb[0], vb[2]);
                mma_f16(o[2*p+1], pf, vb[1], vb[3]);
            }
        }
    }

    const float inv0 = 1.f / l0, inv1 = 1.f / l1;
    uint32_t* A0h = g_Ah + ((size_t)b * 2048 + t0 + lr) * 512 + h * 32;
    uint32_t* A0l = g_Al + ((size_t)b * 2048 + t0 + lr) * 512 + h * 32;
#pragma unroll
    for (int nt = 0; nt < 8; nt++) {
        const int j = nt * 4 + lc;
        uint32_t hh, ll;
        split2(o[nt][0] * inv0, o[nt][1] * inv0, hh, ll);
        A0h[j] = hh; A0l[j] = ll;
        split2(o[nt][2] * inv1, o[nt][3] * inv1, hh, ll);
        A0h[8 * 512 + j] = hh; A0l[8 * 512 + j] = ll;
    }
}

extern "C" void kernel_launch(void* const* d_in, const int* in_sizes, int n_in,
                              void* d_out, int out_size)
{
    const float* query = (const float*)d_in[0];
    const float* key   = (const float*)d_in[1];
    const float* value = (const float*)d_in[2];
    const unsigned char* mask = (const unsigned char*)d_in[3];
    const float* Wq = (const float*)d_in[4];
    const float* Wk = (const float*)d_in[5];
    const float* Wv = (const float*)d_in[6];
    const float* Wo = (const float*)d_in[7];

    const int SMEM_GEMM = 2 * STW * 4;   // 81920 B
    cudaFuncSetAttribute(gemm_qkv,   cudaFuncAttributeMaxDynamicSharedMemorySize, SMEM_GEMM);
    cudaFuncSetAttribute(gemm_oproj, cudaFuncAttributeMaxDynamicSharedMemorySize, SMEM_GEMM);

    zero_flag<<<1, 1>>>();
    mask_scan<<<256, 256>>>((const uint4*)mask, (B_ * T_ * T_) / 16);

    pack_all<<<2048, 256>>>(query, key, value, Wq, Wk, Wv, Wo);

    dim3 gq(24, 32);
    gemm_qkv<<<gq, 256, SMEM_GEMM>>>();

    dim3 gv(32, 32);
    v_pack<<<gv, 128>>>();

    dim3 ga(T_ / 64, B_ * H_);
    flash_attn7<<<ga, 128>>>(mask);

    dim3 go(8, 32);
    gemm_oproj<<<go, 256, SMEM_GEMM>>>((float*)d_out);
}

// round 13
// speedup vs baseline: 1.5969x; 1.1838x over previous
#include <cuda_runtime.h>
#include <cstdint>
#include <math.h>

#define B_  2
#define T_  2048
#define D_  1024
#define H_  16
#define DH  64

// ------------------------- scratch globals -------------------------
// fp16 single-plane (Q/K path)
__device__ uint32_t g_qp[4096*512], g_kp[4096*512];     // inputs q,k packed f16x2
__device__ uint32_t g_Wqp[1024*512], g_Wkp[1024*512];   // Wq, Wk packed f16x2
// bf16 hi/lo planes (V / O path)
__device__ uint32_t g_vh[4096*512], g_vl[4096*512];
__device__ uint32_t g_Wvh[1024*512], g_Wvl[1024*512];
__device__ uint32_t g_Woh[1024*512], g_Wol[1024*512];
// attention operands
__device__ uint32_t g_Qp[B_*H_*T_*32];                 // fp16x2 Q (scaled log2e/8)
__device__ uint32_t g_Kp[B_*H_*T_*32];                 // fp16x2 K
__device__ float    g_V [B_*H_*T_*DH];
__device__ uint32_t g_Vp[(size_t)B_*H_*DH*1024];       // fp16x2 V^T [bh][d][kp]
__device__ uint32_t g_Ah[(size_t)4096*512], g_Al[(size_t)4096*512];
__device__ int      g_mask_any;

// ------------------------- helpers -------------------------
__device__ __forceinline__ uint32_t packbf(float x, float y) {
    uint32_t r; asm("cvt.rn.bf16x2.f32 %0, %1, %2;" : "=r"(r) : "f"(y), "f"(x)); return r;
}
__device__ __forceinline__ uint32_t packh(float x, float y) {
    uint32_t r; asm("cvt.rn.f16x2.f32 %0, %1, %2;" : "=r"(r) : "f"(y), "f"(x)); return r;
}
__device__ __forceinline__ void split2(float x, float y, uint32_t& h, uint32_t& l) {
    h = packbf(x, y);
    float hx = __uint_as_float(h << 16);
    float hy = __uint_as_float(h & 0xFFFF0000u);
    l = packbf(x - hx, y - hy);
}
__device__ __forceinline__ void mma_bf16(float* d, const uint32_t* a, uint32_t b0, uint32_t b1) {
    asm volatile("mma.sync.aligned.m16n8k16.row.col.f32.bf16.bf16.f32 "
        "{%0,%1,%2,%3}, {%4,%5,%6,%7}, {%8,%9}, {%0,%1,%2,%3};"
        : "+f"(d[0]), "+f"(d[1]), "+f"(d[2]), "+f"(d[3])
        : "r"(a[0]), "r"(a[1]), "r"(a[2]), "r"(a[3]), "r"(b0), "r"(b1));
}
__device__ __forceinline__ void mma_f16(float* d, const uint32_t* a, uint32_t b0, uint32_t b1) {
    asm volatile("mma.sync.aligned.m16n8k16.row.col.f32.f16.f16.f32 "
        "{%0,%1,%2,%3}, {%4,%5,%6,%7}, {%8,%9}, {%0,%1,%2,%3};"
        : "+f"(d[0]), "+f"(d[1]), "+f"(d[2]), "+f"(d[3])
        : "r"(a[0]), "r"(a[1]), "r"(a[2]), "r"(a[3]), "r"(b0), "r"(b1));
}
__device__ __forceinline__ void ldx4(uint32_t* r, uint32_t addr) {
    asm volatile("ldmatrix.sync.aligned.m8n8.x4.shared.b16 {%0,%1,%2,%3}, [%4];"
        : "=r"(r[0]), "=r"(r[1]), "=r"(r[2]), "=r"(r[3]) : "r"(addr));
}
__device__ __forceinline__ float ex2(float x) {
    float y; asm("ex2.approx.f32 %0, %1;" : "=f"(y) : "f"(x)); return y;
}
__device__ __forceinline__ uint32_t s2u(const void* p) {
    return (uint32_t)__cvta_generic_to_shared(p);
}
#define CP16(d, s) asm volatile("cp.async.cg.shared.global [%0], [%1], 16;" :: "r"(d), "l"(s))
#define CP_COMMIT  asm volatile("cp.async.commit_group;" ::: "memory")
#define CP_WAIT1   asm volatile("cp.async.wait_group 1;" ::: "memory")
#define CP_WAIT0   asm volatile("cp.async.wait_group 0;" ::: "memory")

// ------------------------- prep kernels -------------------------
__global__ void zero_flag() { g_mask_any = 0; }
__global__ __launch_bounds__(256) void mask_scan(const uint4* __restrict__ m, int n4)
{
    uint32_t acc = 0;
    for (int i = blockIdx.x * 256 + threadIdx.x; i < n4; i += gridDim.x * 256) {
        uint4 v = m[i];
        acc |= v.x | v.y | v.z | v.w;
    }
    acc |= __shfl_xor_sync(0xffffffff, acc, 16);
    acc |= __shfl_xor_sync(0xffffffff, acc, 8);
    acc |= __shfl_xor_sync(0xffffffff, acc, 4);
    acc |= __shfl_xor_sync(0xffffffff, acc, 2);
    acc |= __shfl_xor_sync(0xffffffff, acc, 1);
    if ((threadIdx.x & 31) == 0 && acc) atomicOr(&g_mask_any, 1);
}

__global__ __launch_bounds__(256) void pack_all(
    const float* q, const float* k, const float* v,
    const float* Wq, const float* Wk, const float* Wv, const float* Wo)
{
    const size_t NI = 4096 * 512, NW = 1024 * 512;
    size_t gid = (size_t)blockIdx.x * 256 + threadIdx.x;
    const size_t stride = (size_t)gridDim.x * 256;
    const size_t total = 3 * NI + 4 * NW;
    for (size_t i = gid; i < total; i += stride) {
        if (i < NI) {
            float2 vv = ((const float2*)q)[i];
            g_qp[i] = packh(vv.x, vv.y);
        } else if (i < 2*NI) {
            size_t off = i - NI;
            float2 vv = ((const float2*)k)[off];
            g_kp[off] = packh(vv.x, vv.y);
        } else if (i < 3*NI) {
            size_t off = i - 2*NI;
            float2 vv = ((const float2*)v)[off];
            uint32_t h, l; split2(vv.x, vv.y, h, l);
            g_vh[off] = h; g_vl[off] = l;
        } else if (i < 3*NI+NW) {
            size_t off = i - 3*NI;
            float2 vv = ((const float2*)Wq)[off];
            g_Wqp[off] = packh(vv.x, vv.y);
        } else if (i < 3*NI+2*NW) {
            size_t off = i - 3*NI - NW;
            float2 vv = ((const float2*)Wk)[off];
            g_Wkp[off] = packh(vv.x, vv.y);
        } else if (i < 3*NI+3*NW) {
            size_t off = i - 3*NI - 2*NW;
            float2 vv = ((const float2*)Wv)[off];
            uint32_t h, l; split2(vv.x, vv.y, h, l);
            g_Wvh[off] = h; g_Wvl[off] = l;
        } else {
            size_t off = i - 3*NI - 3*NW;
            float2 vv = ((const float2*)Wo)[off];
            uint32_t h, l; split2(vv.x, vv.y, h, l);
            g_Woh[off] = h; g_Wol[off] = l;
        }
    }
}

__global__ __launch_bounds__(128) void v_pack()
{
    __shared__ float tile[64][65];
    const int tid = threadIdx.x;
    const int bh = blockIdx.y, kt = blockIdx.x * 64;
    const float* Vb = g_V + ((size_t)bh * 2048 + kt) * 64;
#pragma unroll
    for (int i = 0; i < 16; i++) {
        int idx = tid + i * 128;
        int r = idx >> 5, dp = idx & 31;
        float2 v = ((const float2*)Vb)[r * 32 + dp];
        tile[r][dp * 2] = v.x; tile[r][dp * 2 + 1] = v.y;
    }
    __syncthreads();
#pragma unroll
    for (int i = 0; i < 16; i++) {
        int idx = tid + i * 128;
        int d = idx >> 5, kp = idx & 31;
        g_Vp[((size_t)bh * 64 + d) * 1024 + (kt >> 1) + kp] =
            packh(tile[2 * kp][d], tile[2 * kp + 1][d]);
    }
}

// ------------------------- GEMM mainloops -------------------------
#define GSTR 20
#define PLW  (128 * GSTR)
#define STW  (4 * PLW)     // bf16 variant stage (4 planes)
#define STWH (2 * PLW)     // fp16 variant stage (2 planes)

// bf16 3-term (V / O projections)
__device__ __forceinline__ void gemm_mainloop_pl(
    const uint32_t* __restrict__ Ah, const uint32_t* __restrict__ Al,
    const uint32_t* __restrict__ Bh, const uint32_t* __restrict__ Bl,
    int bm, int bn, uint32_t* sm, float acc[4][4][4],
    int wm, int wn, int lane, int tid)
{
    const uint32_t* gAh = Ah + (size_t)bm * 512;
    const uint32_t* gAl = Al + (size_t)bm * 512;
    const uint32_t* gBh = Bh + (size_t)bn * 512;
    const uint32_t* gBl = Bl + (size_t)bn * 512;
    const int pr = tid >> 2, pj = (tid & 3) * 4;

#define GISSUE(it_) do { \
    uint32_t* st_ = sm + ((it_) & 1) * STW; \
    _Pragma("unroll") \
    for (int u_ = 0; u_ < 2; u_++) { \
        const int row_ = pr + u_ * 64; \
        const size_t go_ = (size_t)row_ * 512 + (it_) * 16 + pj; \
        const int so_ = row_ * GSTR + pj; \
        CP16(s2u(&st_[so_]),            &gAh[go_]); \
        CP16(s2u(&st_[PLW + so_]),      &gAl[go_]); \
        CP16(s2u(&st_[2*PLW + so_]),    &gBh[go_]); \
        CP16(s2u(&st_[3*PLW + so_]),    &gBl[go_]); \
    } } while(0)

    const uint32_t smb = s2u(sm);
    const int lrow = (lane & 7) + ((lane >> 3) & 1) * 8;
    const int lseg = (lane >> 4) * 16;

    GISSUE(0); CP_COMMIT;
    for (int it = 0; it < 32; ++it) {
        if (it < 31) { GISSUE(it + 1); CP_COMMIT; CP_WAIT1; }
        else CP_WAIT0;
        __syncthreads();
        const uint32_t stb = smb + ((it & 1) * STW) * 4;
#pragma unroll
        for (int c = 0; c < 2; ++c) {
            uint32_t ah[4][4], al[4][4];
#pragma unroll
            for (int mt = 0; mt < 4; ++mt) {
                uint32_t ra = stb + (uint32_t)((wm + mt * 16 + lrow) * GSTR) * 4 + c * 32 + lseg;
                ldx4(ah[mt], ra);
                ldx4(al[mt], ra + PLW * 4);
            }
#pragma unroll
            for (int p = 0; p < 2; ++p) {
                uint32_t bbh[4], bbl[4];
                uint32_t rb = stb + (uint32_t)(2 * PLW) * 4
                            + (uint32_t)((wn + p * 16 + lrow) * GSTR) * 4 + c * 32 + lseg;
                ldx4(bbh, rb);
                ldx4(bbl, rb + PLW * 4);
#pragma unroll
                for (int mt = 0; mt < 4; ++mt) {
                    mma_bf16(acc[mt][2*p],   ah[mt], bbh[0], bbh[2]);
                    mma_bf16(acc[mt][2*p+1], ah[mt], bbh[1], bbh[3]);
                }
#pragma unroll
                for (int mt = 0; mt < 4; ++mt) {
                    mma_bf16(acc[mt][2*p],   ah[mt], bbl[0], bbl[2]);
                    mma_bf16(acc[mt][2*p+1], ah[mt], bbl[1], bbl[3]);
                }
#pragma unroll
                for (int mt = 0; mt < 4; ++mt) {
                    mma_bf16(acc[mt][2*p],   al[mt], bbh[0], bbh[2]);
                    mma_bf16(acc[mt][2*p+1], al[mt], bbh[1], bbh[3]);
                }
            }
        }
        __syncthreads();
    }
#undef GISSUE
}

// fp16 single-term (Q / K projections)
__device__ __forceinline__ void gemm_mainloop_h(
    const uint32_t* __restrict__ A, const uint32_t* __restrict__ B,
    int bm, int bn, uint32_t* sm, float acc[4][4][4],
    int wm, int wn, int lane, int tid)
{
    const uint32_t* gA = A + (size_t)bm * 512;
    const uint32_t* gB = B + (size_t)bn * 512;
    const int pr = tid >> 2, pj = (tid & 3) * 4;

#define HISSUE(it_) do { \
    uint32_t* st_ = sm + ((it_) & 1) * STWH; \
    _Pragma("unroll") \
    for (int u_ = 0; u_ < 2; u_++) { \
        const int row_ = pr + u_ * 64; \
        const size_t go_ = (size_t)row_ * 512 + (it_) * 16 + pj; \
        const int so_ = row_ * GSTR + pj; \
        CP16(s2u(&st_[so_]),        &gA[go_]); \
        CP16(s2u(&st_[PLW + so_]),  &gB[go_]); \
    } } while(0)

    const uint32_t smb = s2u(sm);
    const int lrow = (lane & 7) + ((lane >> 3) & 1) * 8;
    const int lseg = (lane >> 4) * 16;

    HISSUE(0); CP_COMMIT;
    for (int it = 0; it < 32; ++it) {
        if (it < 31) { HISSUE(it + 1); CP_COMMIT; CP_WAIT1; }
        else CP_WAIT0;
        __syncthreads();
        const uint32_t stb = smb + ((it & 1) * STWH) * 4;
#pragma unroll
        for (int c = 0; c < 2; ++c) {
            uint32_t af[4][4];
#pragma unroll
            for (int mt = 0; mt < 4; ++mt) {
                uint32_t ra = stb + (uint32_t)((wm + mt * 16 + lrow) * GSTR) * 4 + c * 32 + lseg;
                ldx4(af[mt], ra);
            }
#pragma unroll
            for (int p = 0; p < 2; ++p) {
                uint32_t bb[4];
                uint32_t rb = stb + (uint32_t)PLW * 4
                            + (uint32_t)((wn + p * 16 + lrow) * GSTR) * 4 + c * 32 + lseg;
                ldx4(bb, rb);
#pragma unroll
                for (int mt = 0; mt < 4; ++mt) {
                    mma_f16(acc[mt][2*p],   af[mt], bb[0], bb[2]);
                    mma_f16(acc[mt][2*p+1], af[mt], bb[1], bb[3]);
                }
            }
        }
        __syncthreads();
    }
#undef HISSUE
}

// ------------------------- fused QKV projection -------------------------
#define QSCALE 0.18033688f   // (1/8) * log2(e)
__global__ __launch_bounds__(256, 2) void gemm_qkv()
{
    extern __shared__ __align__(16) uint32_t smw[];
    const int which = blockIdx.x >> 3;
    const int bn = (blockIdx.x & 7) * 128;
    const int bm = blockIdx.y * 128;

    const int tid = threadIdx.x;
    const int wid = tid >> 5, lane = tid & 31;
    const int wm = (wid & 1) * 64, wn = (wid >> 1) * 32;
    const int lr = lane >> 2, lc = lane & 3;

    float acc[4][4][4];
#pragma unroll
    for (int mt = 0; mt < 4; mt++)
#pragma unroll
        for (int nt = 0; nt < 4; nt++)
#pragma unroll
            for (int i = 0; i < 4; i++) acc[mt][nt][i] = 0.f;

    if (which < 2) {
        const uint32_t* A = which == 0 ? g_qp : g_kp;
        const uint32_t* B = which == 0 ? g_Wqp : g_Wkp;
        gemm_mainloop_h(A, B, bm, bn, smw, acc, wm, wn, lane, tid);
        uint32_t* P = which == 0 ? g_Qp : g_Kp;
        const float sc = which == 0 ? QSCALE : 1.0f;
#pragma unroll
        for (int mt = 0; mt < 4; ++mt)
#pragma unroll
            for (int nt = 0; nt < 4; ++nt) {
                const int row  = bm + wm + mt * 16 + lr;
                const int col0 = bn + wn + nt * 8 + lc * 2;
                const int hh = col0 >> 6, j = (col0 & 63) >> 1;
                const float* d = acc[mt][nt];
                int b = row >> 11, t = row & 2047;
                P[((size_t)(b * 16 + hh) * 2048 + t) * 32 + j] = packh(d[0] * sc, d[1] * sc);
                b = (row + 8) >> 11; t = (row + 8) & 2047;
                P[((size_t)(b * 16 + hh) * 2048 + t) * 32 + j] = packh(d[2] * sc, d[3] * sc);
            }
    } else {
        gemm_mainloop_pl(g_vh, g_vl, g_Wvh, g_Wvl, bm, bn, smw, acc, wm, wn, lane, tid);
#pragma unroll
        for (int mt = 0; mt < 4; ++mt)
#pragma unroll
            for (int nt = 0; nt < 4; ++nt) {
                const int row  = bm + wm + mt * 16 + lr;
                const int col0 = bn + wn + nt * 8 + lc * 2;
                const int hh = col0 >> 6, dd = col0 & 63;
                const float* d = acc[mt][nt];
                int b = row >> 11, t = row & 2047;
                *(float2*)(g_V + (((size_t)(b * 16 + hh) * 2048 + t) * 64 + dd)) = make_float2(d[0], d[1]);
                b = (row + 8) >> 11; t = (row + 8) & 2047;
                *(float2*)(g_V + (((size_t)(b * 16 + hh) * 2048 + t) * 64 + dd)) = make_float2(d[2], d[3]);
            }
    }
}

// ------------------------- output projection -------------------------
__global__ __launch_bounds__(256, 2) void gemm_oproj(float* __restrict__ C)
{
    extern __shared__ __align__(16) uint32_t smw[];
    const int bn = blockIdx.x * 128;
    const int bm = blockIdx.y * 128;
    const int tid = threadIdx.x;
    const int wid = tid >> 5, lane = tid & 31;
    const int wm = (wid & 1) * 64, wn = (wid >> 1) * 32;
    const int lr = lane >> 2, lc = lane & 3;

    float acc[4][4][4];
#pragma unroll
    for (int mt = 0; mt < 4; mt++)
#pragma unroll
        for (int nt = 0; nt < 4; nt++)
#pragma unroll
            for (int i = 0; i < 4; i++) acc[mt][nt][i] = 0.f;

    gemm_mainloop_pl(g_Ah, g_Al, g_Woh, g_Wol, bm, bn, smw, acc, wm, wn, lane, tid);

#pragma unroll
    for (int mt = 0; mt < 4; ++mt)
#pragma unroll
        for (int nt = 0; nt < 4; ++nt) {
            const int row  = bm + wm + mt * 16 + lr;
            const int col0 = bn + wn + nt * 8 + lc * 2;
            const float* d = acc[mt][nt];
            *(float2*)(C + (size_t)row * 1024 + col0)       = make_float2(d[0], d[1]);
            *(float2*)(C + (size_t)(row + 8) * 1024 + col0) = make_float2(d[2], d[3]);
        }
}

// ------------------------- flash attention: fp16 single-term (unchanged R12 winner) -------------------------
#define KSTR 36
__global__ __launch_bounds__(128, 4) void flash_attn7(
    const unsigned char* __restrict__ mask)
{
    __shared__ __align__(16) uint32_t SK[64*KSTR], SV[64*KSTR];

    const int tid = threadIdx.x;
    const int w = tid >> 5, lane = tid & 31;
    const int lr = lane >> 2, lc = lane & 3;
    const int bh = blockIdx.y, b = bh >> 4, h = bh & 15;
    const int q0 = blockIdx.x * 64;
    const int t0 = q0 + w * 16;
    const bool anymask = (g_mask_any != 0);

    uint32_t qf[4][4];
    {
        const uint32_t* q0p = g_Qp + ((size_t)bh * 2048 + t0 + lr) * 32;
        const uint32_t* q1p = q0p + 8 * 32;
#pragma unroll
        for (int c = 0; c < 4; c++) {
            const int j = c * 8 + lc;
            qf[c][0] = q0p[j];     qf[c][1] = q1p[j];
            qf[c][2] = q0p[j + 4]; qf[c][3] = q1p[j + 4];
        }
    }

    float m0 = -1e30f, m1 = -1e30f, l0 = 0.f, l1 = 0.f;
    float o[8][4];
#pragma unroll
    for (int nt = 0; nt < 8; nt++)
#pragma unroll
        for (int i = 0; i < 4; i++) o[nt][i] = 0.f;

    const unsigned char* mrow0 = mask + ((size_t)b * 2048 + t0 + lr) * 2048;
    const unsigned char* mrow1 = mrow0 + 8 * 2048;

    const uint32_t sk = s2u(SK), sv = s2u(SV);
    const int lrow = (lane & 7) + ((lane >> 3) & 1) * 8;
    const int lseg = (lane >> 4) * 16;

    for (int kt = 0; kt < 2048; kt += 64) {
        __syncthreads();
        {
            const uint32_t* KP = g_Kp + ((size_t)bh * 2048 + kt) * 32;
            const uint32_t* VP = g_Vp + (size_t)bh * 64 * 1024 + (kt >> 1);
#pragma unroll
            for (int i = 0; i < 4; i++) {
                int idx = tid + i * 128;
                int r = idx >> 3, j4 = (idx & 7) * 4;
                *(uint4*)&SK[r * KSTR + j4] = *(const uint4*)&KP[r * 32 + j4];
                *(uint4*)&SV[r * KSTR + j4] = *(const uint4*)&VP[(size_t)r * 1024 + j4];
            }
        }
        __syncthreads();

        float s[8][4];
#pragma unroll
        for (int nt = 0; nt < 8; nt++)
#pragma unroll
            for (int i = 0; i < 4; i++) s[nt][i] = 0.f;
#pragma unroll
        for (int c = 0; c < 4; c++) {
#pragma unroll
            for (int p = 0; p < 4; p++) {
                uint32_t kb[4];
                uint32_t ra = (uint32_t)((p * 16 + lrow) * KSTR) * 4 + c * 32 + lseg;
                ldx4(kb, sk + ra);
                mma_f16(s[2*p],   qf[c], kb[0], kb[2]);
                mma_f16(s[2*p+1], qf[c], kb[1], kb[3]);
            }
        }

        if (anymask) {
#pragma unroll
            for (int nt = 0; nt < 8; nt++) {
                const int cc = kt + nt * 8 + lc * 2;
                if (mrow0[cc])     s[nt][0] = -1e30f;
                if (mrow0[cc + 1]) s[nt][1] = -1e30f;
                if (mrow1[cc])     s[nt][2] = -1e30f;
                if (mrow1[cc + 1]) s[nt][3] = -1e30f;
            }
        }

        float tm0 = -1e30f, tm1 = -1e30f;
#pragma unroll
        for (int nt = 0; nt < 8; nt++) {
            tm0 = fmaxf(tm0, fmaxf(s[nt][0], s[nt][1]));
            tm1 = fmaxf(tm1, fmaxf(s[nt][2], s[nt][3]));
        }
        tm0 = fmaxf(tm0, __shfl_xor_sync(0xffffffff, tm0, 1));
        tm0 = fmaxf(tm0, __shfl_xor_sync(0xffffffff, tm0, 2));
        tm1 = fmaxf(tm1, __shfl_xor_sync(0xffffffff, tm1, 1));
        tm1 = fmaxf(tm1, __shfl_xor_sync(0xffffffff, tm1, 2));
        float mn0 = fmaxf(m0, tm0), mn1 = fmaxf(m1, tm1);
        float cr0 = ex2(m0 - mn0), cr1 = ex2(m1 - mn1);
        m0 = mn0; m1 = mn1;
        float ts0 = 0.f, ts1 = 0.f;
#pragma unroll
        for (int nt = 0; nt < 8; nt++) {
            s[nt][0] = ex2(s[nt][0] - mn0);
            s[nt][1] = ex2(s[nt][1] - mn0);
            s[nt][2] = ex2(s[nt][2] - mn1);
            s[nt][3] = ex2(s[nt][3] - mn1);
            ts0 += s[nt][0] + s[nt][1];
            ts1 += s[nt][2] + s[nt][3];
        }
        ts0 += __shfl_xor_sync(0xffffffff, ts0, 1);
        ts0 += __shfl_xor_sync(0xffffffff, ts0, 2);
        ts1 += __shfl_xor_sync(0xffffffff, ts1, 1);
        ts1 += __shfl_xor_sync(0xffffffff, ts1, 2);
        l0 = l0 * cr0 + ts0;
        l1 = l1 * cr1 + ts1;
#pragma unroll
        for (int nt = 0; nt < 8; nt++) {
            o[nt][0] *= cr0; o[nt][1] *= cr0;
            o[nt][2] *= cr1; o[nt][3] *= cr1;
        }

#pragma unroll
        for (int kc = 0; kc < 4; kc++) {
            uint32_t pf[4];
            pf[0] = packh(s[2*kc][0],   s[2*kc][1]);
            pf[1] = packh(s[2*kc][2],   s[2*kc][3]);
            pf[2] = packh(s[2*kc+1][0], s[2*kc+1][1]);
            pf[3] = packh(s[2*kc+1][2], s[2*kc+1][3]);
#pragma unroll
            for (int p = 0; p < 4; p++) {
                uint32_t vb[4];
                uint32_t ra = (uint32_t)((p * 16 + lrow) * KSTR) * 4 + kc * 32 + lseg;
                ldx4(vb, sv + ra);
                mma_f16(o[2*p],   pf, vb[0], vb[2]);
                mma_f16(o[2*p+1], pf, vb[1], vb[3]);
            }
        }
    }

    const float inv0 = 1.f / l0, inv1 = 1.f / l1;
    uint32_t* A0h = g_Ah + ((size_t)b * 2048 + t0 + lr) * 512 + h * 32;
    uint32_t* A0l = g_Al + ((size_t)b * 2048 + t0 + lr) * 512 + h * 32;
#pragma unroll
    for (int nt = 0; nt < 8; nt++) {
        const int j = nt * 4 + lc;
        uint32_t hh, ll;
        split2(o[nt][0] * inv0, o[nt][1] * inv0, hh, ll);
        A0h[j] = hh; A0l[j] = ll;
        split2(o[nt][2] * inv1, o[nt][3] * inv1, hh, ll);
        A0h[8 * 512 + j] = hh; A0l[8 * 512 + j] = ll;
    }
}

extern "C" void kernel_launch(void* const* d_in, const int* in_sizes, int n_in,
                              void* d_out, int out_size)
{
    const float* query = (const float*)d_in[0];
    const float* key   = (const float*)d_in[1];
    const float* value = (const float*)d_in[2];
    const unsigned char* mask = (const unsigned char*)d_in[3];
    const float* Wq = (const float*)d_in[4];
    const float* Wk = (const float*)d_in[5];
    const float* Wv = (const float*)d_in[6];
    const float* Wo = (const float*)d_in[7];

    const int SMEM_GEMM = 2 * STW * 4;   // 81920 B (bf16 variant size; fp16 uses less)
    cudaFuncSetAttribute(gemm_qkv,   cudaFuncAttributeMaxDynamicSharedMemorySize, SMEM_GEMM);
    cudaFuncSetAttribute(gemm_oproj, cudaFuncAttributeMaxDynamicSharedMemorySize, SMEM_GEMM);

    zero_flag<<<1, 1>>>();
    mask_scan<<<256, 256>>>((const uint4*)mask, (B_ * T_ * T_) / 16);

    pack_all<<<2048, 256>>>(query, key, value, Wq, Wk, Wv, Wo);

    dim3 gq(24, 32);
    gemm_qkv<<<gq, 256, SMEM_GEMM>>>();

    dim3 gv(32, 32);
    v_pack<<<gv, 128>>>();

    dim3 ga(T_ / 64, B_ * H_);
    flash_attn7<<<ga, 128>>>(mask);

    dim3 go(8, 32);
    gemm_oproj<<<go, 256, SMEM_GEMM>>>((float*)d_out);
}

// round 14
// speedup vs baseline: 1.8576x; 1.1632x over previous
#include <cuda_runtime.h>
#include <cuda_fp16.h>
#include <cstdint>
#include <math.h>

#define B_  2
#define T_  2048
#define D_  1024
#define H_  16
#define DH  64

// ------------------------- scratch globals -------------------------
// fp16 single-plane (Q/K path)
__device__ uint32_t g_qp[4096*512], g_kp[4096*512];
__device__ uint32_t g_Wqp[1024*512], g_Wkp[1024*512];
// fp16 split-A planes (V / O path)
__device__ uint32_t g_vh[4096*512], g_vl[4096*512];    // v input fp16 hi/lo
__device__ uint32_t g_Wvp[1024*512];                   // Wv single fp16
__device__ uint32_t g_Wop[1024*512];                   // Wo single fp16
// attention operands
__device__ uint32_t g_Qp[B_*H_*T_*32];                 // fp16x2 Q (scaled log2e/8)
__device__ uint32_t g_Kp[B_*H_*T_*32];                 // fp16x2 K
__device__ float    g_V [B_*H_*T_*DH];
__device__ uint32_t g_Vp[(size_t)B_*H_*DH*1024];       // fp16x2 V^T [bh][d][kp]
__device__ uint32_t g_Ah[(size_t)4096*512], g_Al[(size_t)4096*512];  // attn out fp16 hi/lo
__device__ int      g_mask_any;

// ------------------------- helpers -------------------------
__device__ __forceinline__ uint32_t packh(float x, float y) {
    uint32_t r; asm("cvt.rn.f16x2.f32 %0, %1, %2;" : "=r"(r) : "f"(y), "f"(x)); return r;
}
// fp16 hi/lo split: x = hi + lo captures ~22 mantissa bits
__device__ __forceinline__ void split2h(float x, float y, uint32_t& h, uint32_t& l) {
    h = packh(x, y);
    __half2 hv = *reinterpret_cast<__half2*>(&h);
    l = packh(x - __half2float(hv.x), y - __half2float(hv.y));
}
__device__ __forceinline__ void mma_f16(float* d, const uint32_t* a, uint32_t b0, uint32_t b1) {
    asm volatile("mma.sync.aligned.m16n8k16.row.col.f32.f16.f16.f32 "
        "{%0,%1,%2,%3}, {%4,%5,%6,%7}, {%8,%9}, {%0,%1,%2,%3};"
        : "+f"(d[0]), "+f"(d[1]), "+f"(d[2]), "+f"(d[3])
        : "r"(a[0]), "r"(a[1]), "r"(a[2]), "r"(a[3]), "r"(b0), "r"(b1));
}
__device__ __forceinline__ void ldx4(uint32_t* r, uint32_t addr) {
    asm volatile("ldmatrix.sync.aligned.m8n8.x4.shared.b16 {%0,%1,%2,%3}, [%4];"
        : "=r"(r[0]), "=r"(r[1]), "=r"(r[2]), "=r"(r[3]) : "r"(addr));
}
__device__ __forceinline__ float ex2(float x) {
    float y; asm("ex2.approx.f32 %0, %1;" : "=f"(y) : "f"(x)); return y;
}
__device__ __forceinline__ uint32_t s2u(const void* p) {
    return (uint32_t)__cvta_generic_to_shared(p);
}
#define CP16(d, s) asm volatile("cp.async.cg.shared.global [%0], [%1], 16;" :: "r"(d), "l"(s))
#define CP_COMMIT  asm volatile("cp.async.commit_group;" ::: "memory")
#define CP_WAIT1   asm volatile("cp.async.wait_group 1;" ::: "memory")
#define CP_WAIT0   asm volatile("cp.async.wait_group 0;" ::: "memory")

// ------------------------- prep kernels -------------------------
__global__ void zero_flag() { g_mask_any = 0; }
__global__ __launch_bounds__(256) void mask_scan(const uint4* __restrict__ m, int n4)
{
    uint32_t acc = 0;
    for (int i = blockIdx.x * 256 + threadIdx.x; i < n4; i += gridDim.x * 256) {
        uint4 v = m[i];
        acc |= v.x | v.y | v.z | v.w;
    }
    acc |= __shfl_xor_sync(0xffffffff, acc, 16);
    acc |= __shfl_xor_sync(0xffffffff, acc, 8);
    acc |= __shfl_xor_sync(0xffffffff, acc, 4);
    acc |= __shfl_xor_sync(0xffffffff, acc, 2);
    acc |= __shfl_xor_sync(0xffffffff, acc, 1);
    if ((threadIdx.x & 31) == 0 && acc) atomicOr(&g_mask_any, 1);
}

__global__ __launch_bounds__(256) void pack_all(
    const float* q, const float* k, const float* v,
    const float* Wq, const float* Wk, const float* Wv, const float* Wo)
{
    const size_t NI = 4096 * 512, NW = 1024 * 512;
    size_t gid = (size_t)blockIdx.x * 256 + threadIdx.x;
    const size_t stride = (size_t)gridDim.x * 256;
    const size_t total = 3 * NI + 4 * NW;
    for (size_t i = gid; i < total; i += stride) {
        if (i < NI) {
            float2 vv = ((const float2*)q)[i];
            g_qp[i] = packh(vv.x, vv.y);
        } else if (i < 2*NI) {
            size_t off = i - NI;
            float2 vv = ((const float2*)k)[off];
            g_kp[off] = packh(vv.x, vv.y);
        } else if (i < 3*NI) {
            size_t off = i - 2*NI;
            float2 vv = ((const float2*)v)[off];
            uint32_t h, l; split2h(vv.x, vv.y, h, l);
            g_vh[off] = h; g_vl[off] = l;
        } else if (i < 3*NI+NW) {
            size_t off = i - 3*NI;
            float2 vv = ((const float2*)Wq)[off];
            g_Wqp[off] = packh(vv.x, vv.y);
        } else if (i < 3*NI+2*NW) {
            size_t off = i - 3*NI - NW;
            float2 vv = ((const float2*)Wk)[off];
            g_Wkp[off] = packh(vv.x, vv.y);
        } else if (i < 3*NI+3*NW) {
            size_t off = i - 3*NI - 2*NW;
            float2 vv = ((const float2*)Wv)[off];
            g_Wvp[off] = packh(vv.x, vv.y);
        } else {
            size_t off = i - 3*NI - 3*NW;
            float2 vv = ((const float2*)Wo)[off];
            g_Wop[off] = packh(vv.x, vv.y);
        }
    }
}

__global__ __launch_bounds__(128) void v_pack()
{
    __shared__ float tile[64][65];
    const int tid = threadIdx.x;
    const int bh = blockIdx.y, kt = blockIdx.x * 64;
    const float* Vb = g_V + ((size_t)bh * 2048 + kt) * 64;
#pragma unroll
    for (int i = 0; i < 16; i++) {
        int idx = tid + i * 128;
        int r = idx >> 5, dp = idx & 31;
        float2 v = ((const float2*)Vb)[r * 32 + dp];
        tile[r][dp * 2] = v.x; tile[r][dp * 2 + 1] = v.y;
    }
    __syncthreads();
#pragma unroll
    for (int i = 0; i < 16; i++) {
        int idx = tid + i * 128;
        int d = idx >> 5, kp = idx & 31;
        g_Vp[((size_t)bh * 64 + d) * 1024 + (kt >> 1) + kp] =
            packh(tile[2 * kp][d], tile[2 * kp + 1][d]);
    }
}

// ------------------------- GEMM mainloops -------------------------
#define GSTR 20
#define PLW  (128 * GSTR)
#define STWH (2 * PLW)     // fp16 single stage (A, B)
#define STW2 (3 * PLW)     // fp16 split-A stage (Ah, Al, B)

// fp16 single-term (Q / K projections)
__device__ __forceinline__ void gemm_mainloop_h(
    const uint32_t* __restrict__ A, const uint32_t* __restrict__ B,
    int bm, int bn, uint32_t* sm, float acc[4][4][4],
    int wm, int wn, int lane, int tid)
{
    const uint32_t* gA = A + (size_t)bm * 512;
    const uint32_t* gB = B + (size_t)bn * 512;
    const int pr = tid >> 2, pj = (tid & 3) * 4;

#define HISSUE(it_) do { \
    uint32_t* st_ = sm + ((it_) & 1) * STWH; \
    _Pragma("unroll") \
    for (int u_ = 0; u_ < 2; u_++) { \
        const int row_ = pr + u_ * 64; \
        const size_t go_ = (size_t)row_ * 512 + (it_) * 16 + pj; \
        const int so_ = row_ * GSTR + pj; \
        CP16(s2u(&st_[so_]),        &gA[go_]); \
        CP16(s2u(&st_[PLW + so_]),  &gB[go_]); \
    } } while(0)

    const uint32_t smb = s2u(sm);
    const int lrow = (lane & 7) + ((lane >> 3) & 1) * 8;
    const int lseg = (lane >> 4) * 16;

    HISSUE(0); CP_COMMIT;
    for (int it = 0; it < 32; ++it) {
        if (it < 31) { HISSUE(it + 1); CP_COMMIT; CP_WAIT1; }
        else CP_WAIT0;
        __syncthreads();
        const uint32_t stb = smb + ((it & 1) * STWH) * 4;
#pragma unroll
        for (int c = 0; c < 2; ++c) {
            uint32_t af[4][4];
#pragma unroll
            for (int mt = 0; mt < 4; ++mt) {
                uint32_t ra = stb + (uint32_t)((wm + mt * 16 + lrow) * GSTR) * 4 + c * 32 + lseg;
                ldx4(af[mt], ra);
            }
#pragma unroll
            for (int p = 0; p < 2; ++p) {
                uint32_t bb[4];
                uint32_t rb = stb + (uint32_t)PLW * 4
                            + (uint32_t)((wn + p * 16 + lrow) * GSTR) * 4 + c * 32 + lseg;
                ldx4(bb, rb);
#pragma unroll
                for (int mt = 0; mt < 4; ++mt) {
                    mma_f16(acc[mt][2*p],   af[mt], bb[0], bb[2]);
                    mma_f16(acc[mt][2*p+1], af[mt], bb[1], bb[3]);
                }
            }
        }
        __syncthreads();
    }
#undef HISSUE
}

// fp16 split-A 2-term (V / O projections): D = (Ah + Al) @ B
__device__ __forceinline__ void gemm_mainloop_h2(
    const uint32_t* __restrict__ Ah, const uint32_t* __restrict__ Al,
    const uint32_t* __restrict__ B,
    int bm, int bn, uint32_t* sm, float acc[4][4][4],
    int wm, int wn, int lane, int tid)
{
    const uint32_t* gAh = Ah + (size_t)bm * 512;
    const uint32_t* gAl = Al + (size_t)bm * 512;
    const uint32_t* gB  = B  + (size_t)bn * 512;
    const int pr = tid >> 2, pj = (tid & 3) * 4;

#define H2ISSUE(it_) do { \
    uint32_t* st_ = sm + ((it_) & 1) * STW2; \
    _Pragma("unroll") \
    for (int u_ = 0; u_ < 2; u_++) { \
        const int row_ = pr + u_ * 64; \
        const size_t go_ = (size_t)row_ * 512 + (it_) * 16 + pj; \
        const int so_ = row_ * GSTR + pj; \
        CP16(s2u(&st_[so_]),            &gAh[go_]); \
        CP16(s2u(&st_[PLW + so_]),      &gAl[go_]); \
        CP16(s2u(&st_[2*PLW + so_]),    &gB[go_]); \
    } } while(0)

    const uint32_t smb = s2u(sm);
    const int lrow = (lane & 7) + ((lane >> 3) & 1) * 8;
    const int lseg = (lane >> 4) * 16;

    H2ISSUE(0); CP_COMMIT;
    for (int it = 0; it < 32; ++it) {
        if (it < 31) { H2ISSUE(it + 1); CP_COMMIT; CP_WAIT1; }
        else CP_WAIT0;
        __syncthreads();
        const uint32_t stb = smb + ((it & 1) * STW2) * 4;
#pragma unroll
        for (int c = 0; c < 2; ++c) {
            uint32_t ah[4][4], al[4][4];
#pragma unroll
            for (int mt = 0; mt < 4; ++mt) {
                uint32_t ra = stb + (uint32_t)((wm + mt * 16 + lrow) * GSTR) * 4 + c * 32 + lseg;
                ldx4(ah[mt], ra);
                ldx4(al[mt], ra + PLW * 4);
            }
#pragma unroll
            for (int p = 0; p < 2; ++p) {
                uint32_t bb[4];
                uint32_t rb = stb + (uint32_t)(2 * PLW) * 4
                            + (uint32_t)((wn + p * 16 + lrow) * GSTR) * 4 + c * 32 + lseg;
                ldx4(bb, rb);
#pragma unroll
                for (int mt = 0; mt < 4; ++mt) {
                    mma_f16(acc[mt][2*p],   ah[mt], bb[0], bb[2]);
                    mma_f16(acc[mt][2*p+1], ah[mt], bb[1], bb[3]);
                }
#pragma unroll
                for (int mt = 0; mt < 4; ++mt) {
                    mma_f16(acc[mt][2*p],   al[mt], bb[0], bb[2]);
                    mma_f16(acc[mt][2*p+1], al[mt], bb[1], bb[3]);
                }
            }
        }
        __syncthreads();
    }
#undef H2ISSUE
}

// ------------------------- fused QKV projection -------------------------
#define QSCALE 0.18033688f   // (1/8) * log2(e)
__global__ __launch_bounds__(256, 2) void gemm_qkv()
{
    extern __shared__ __align__(16) uint32_t smw[];
    const int which = blockIdx.x >> 3;
    const int bn = (blockIdx.x & 7) * 128;
    const int bm = blockIdx.y * 128;

    const int tid = threadIdx.x;
    const int wid = tid >> 5, lane = tid & 31;
    const int wm = (wid & 1) * 64, wn = (wid >> 1) * 32;
    const int lr = lane >> 2, lc = lane & 3;

    float acc[4][4][4];
#pragma unroll
    for (int mt = 0; mt < 4; mt++)
#pragma unroll
        for (int nt = 0; nt < 4; nt++)
#pragma unroll
            for (int i = 0; i < 4; i++) acc[mt][nt][i] = 0.f;

    if (which < 2) {
        const uint32_t* A = which == 0 ? g_qp : g_kp;
        const uint32_t* B = which == 0 ? g_Wqp : g_Wkp;
        gemm_mainloop_h(A, B, bm, bn, smw, acc, wm, wn, lane, tid);
        uint32_t* P = which == 0 ? g_Qp : g_Kp;
        const float sc = which == 0 ? QSCALE : 1.0f;
#pragma unroll
        for (int mt = 0; mt < 4; ++mt)
#pragma unroll
            for (int nt = 0; nt < 4; ++nt) {
                const int row  = bm + wm + mt * 16 + lr;
                const int col0 = bn + wn + nt * 8 + lc * 2;
                const int hh = col0 >> 6, j = (col0 & 63) >> 1;
                const float* d = acc[mt][nt];
                int b = row >> 11, t = row & 2047;
                P[((size_t)(b * 16 + hh) * 2048 + t) * 32 + j] = packh(d[0] * sc, d[1] * sc);
                b = (row + 8) >> 11; t = (row + 8) & 2047;
                P[((size_t)(b * 16 + hh) * 2048 + t) * 32 + j] = packh(d[2] * sc, d[3] * sc);
            }
    } else {
        gemm_mainloop_h2(g_vh, g_vl, g_Wvp, bm, bn, smw, acc, wm, wn, lane, tid);
#pragma unroll
        for (int mt = 0; mt < 4; ++mt)
#pragma unroll
            for (int nt = 0; nt < 4; ++nt) {
                const int row  = bm + wm + mt * 16 + lr;
                const int col0 = bn + wn + nt * 8 + lc * 2;
                const int hh = col0 >> 6, dd = col0 & 63;
                const float* d = acc[mt][nt];
                int b = row >> 11, t = row & 2047;
                *(float2*)(g_V + (((size_t)(b * 16 + hh) * 2048 + t) * 64 + dd)) = make_float2(d[0], d[1]);
                b = (row + 8) >> 11; t = (row + 8) & 2047;
                *(float2*)(g_V + (((size_t)(b * 16 + hh) * 2048 + t) * 64 + dd)) = make_float2(d[2], d[3]);
            }
    }
}

// ------------------------- output projection -------------------------
__global__ __launch_bounds__(256, 2) void gemm_oproj(float* __restrict__ C)
{
    extern __shared__ __align__(16) uint32_t smw[];
    const int bn = blockIdx.x * 128;
    const int bm = blockIdx.y * 128;
    const int tid = threadIdx.x;
    const int wid = tid >> 5, lane = tid & 31;
    const int wm = (wid & 1) * 64, wn = (wid >> 1) * 32;
    const int lr = lane >> 2, lc = lane & 3;

    float acc[4][4][4];
#pragma unroll
    for (int mt = 0; mt < 4; mt++)
#pragma unroll
        for (int nt = 0; nt < 4; nt++)
#pragma unroll
            for (int i = 0; i < 4; i++) acc[mt][nt][i] = 0.f;

    gemm_mainloop_h2(g_Ah, g_Al, g_Wop, bm, bn, smw, acc, wm, wn, lane, tid);

#pragma unroll
    for (int mt = 0; mt < 4; ++mt)
#pragma unroll
        for (int nt = 0; nt < 4; ++nt) {
            const int row  = bm + wm + mt * 16 + lr;
            const int col0 = bn + wn + nt * 8 + lc * 2;
            const float* d = acc[mt][nt];
            *(float2*)(C + (size_t)row * 1024 + col0)       = make_float2(d[0], d[1]);
            *(float2*)(C + (size_t)(row + 8) * 1024 + col0) = make_float2(d[2], d[3]);
        }
}

// ------------------------- flash attention: fp16 single-term -------------------------
#define KSTR 36
__global__ __launch_bounds__(128, 4) void flash_attn7(
    const unsigned char* __restrict__ mask)
{
    __shared__ __align__(16) uint32_t SK[64*KSTR], SV[64*KSTR];

    const int tid = threadIdx.x;
    const int w = tid >> 5, lane = tid & 31;
    const int lr = lane >> 2, lc = lane & 3;
    const int bh = blockIdx.y, b = bh >> 4, h = bh & 15;
    const int q0 = blockIdx.x * 64;
    const int t0 = q0 + w * 16;
    const bool anymask = (g_mask_any != 0);

    uint32_t qf[4][4];
    {
        const uint32_t* q0p = g_Qp + ((size_t)bh * 2048 + t0 + lr) * 32;
        const uint32_t* q1p = q0p + 8 * 32;
#pragma unroll
        for (int c = 0; c < 4; c++) {
            const int j = c * 8 + lc;
            qf[c][0] = q0p[j];     qf[c][1] = q1p[j];
            qf[c][2] = q0p[j + 4]; qf[c][3] = q1p[j + 4];
        }
    }

    float m0 = -1e30f, m1 = -1e30f, l0 = 0.f, l1 = 0.f;
    float o[8][4];
#pragma unroll
    for (int nt = 0; nt < 8; nt++)
#pragma unroll
        for (int i = 0; i < 4; i++) o[nt][i] = 0.f;

    const unsigned char* mrow0 = mask + ((size_t)b * 2048 + t0 + lr) * 2048;
    const unsigned char* mrow1 = mrow0 + 8 * 2048;

    const uint32_t sk = s2u(SK), sv = s2u(SV);
    const int lrow = (lane & 7) + ((lane >> 3) & 1) * 8;
    const int lseg = (lane >> 4) * 16;

    for (int kt = 0; kt < 2048; kt += 64) {
        __syncthreads();
        {
            const uint32_t* KP = g_Kp + ((size_t)bh * 2048 + kt) * 32;
            const uint32_t* VP = g_Vp + (size_t)bh * 64 * 1024 + (kt >> 1);
#pragma unroll
            for (int i = 0; i < 4; i++) {
                int idx = tid + i * 128;
                int r = idx >> 3, j4 = (idx & 7) * 4;
                *(uint4*)&SK[r * KSTR + j4] = *(const uint4*)&KP[r * 32 + j4];
                *(uint4*)&SV[r * KSTR + j4] = *(const uint4*)&VP[(size_t)r * 1024 + j4];
            }
        }
        __syncthreads();

        float s[8][4];
#pragma unroll
        for (int nt = 0; nt < 8; nt++)
#pragma unroll
            for (int i = 0; i < 4; i++) s[nt][i] = 0.f;
#pragma unroll
        for (int c = 0; c < 4; c++) {
#pragma unroll
            for (int p = 0; p < 4; p++) {
                uint32_t kb[4];
                uint32_t ra = (uint32_t)((p * 16 + lrow) * KSTR) * 4 + c * 32 + lseg;
                ldx4(kb, sk + ra);
                mma_f16(s[2*p],   qf[c], kb[0], kb[2]);
                mma_f16(s[2*p+1], qf[c], kb[1], kb[3]);
            }
        }

        if (anymask) {
#pragma unroll
            for (int nt = 0; nt < 8; nt++) {
                const int cc = kt + nt * 8 + lc * 2;
                if (mrow0[cc])     s[nt][0] = -1e30f;
                if (mrow0[cc + 1]) s[nt][1] = -1e30f;
                if (mrow1[cc])     s[nt][2] = -1e30f;
                if (mrow1[cc + 1]) s[nt][3] = -1e30f;
            }
        }

        float tm0 = -1e30f, tm1 = -1e30f;
#pragma unroll
        for (int nt = 0; nt < 8; nt++) {
            tm0 = fmaxf(tm0, fmaxf(s[nt][0], s[nt][1]));
            tm1 = fmaxf(tm1, fmaxf(s[nt][2], s[nt][3]));
        }
        tm0 = fmaxf(tm0, __shfl_xor_sync(0xffffffff, tm0, 1));
        tm0 = fmaxf(tm0, __shfl_xor_sync(0xffffffff, tm0, 2));
        tm1 = fmaxf(tm1, __shfl_xor_sync(0xffffffff, tm1, 1));
        tm1 = fmaxf(tm1, __shfl_xor_sync(0xffffffff, tm1, 2));
        float mn0 = fmaxf(m0, tm0), mn1 = fmaxf(m1, tm1);
        float cr0 = ex2(m0 - mn0), cr1 = ex2(m1 - mn1);
        m0 = mn0; m1 = mn1;
        float ts0 = 0.f, ts1 = 0.f;
#pragma unroll
        for (int nt = 0; nt < 8; nt++) {
            s[nt][0] = ex2(s[nt][0] - mn0);
            s[nt][1] = ex2(s[nt][1] - mn0);
            s[nt][2] = ex2(s[nt][2] - mn1);
            s[nt][3] = ex2(s[nt][3] - mn1);
            ts0 += s[nt][0] + s[nt][1];
            ts1 += s[nt][2] + s[nt][3];
        }
        ts0 += __shfl_xor_sync(0xffffffff, ts0, 1);
        ts0 += __shfl_xor_sync(0xffffffff, ts0, 2);
        ts1 += __shfl_xor_sync(0xffffffff, ts1, 1);
        ts1 += __shfl_xor_sync(0xffffffff, ts1, 2);
        l0 = l0 * cr0 + ts0;
        l1 = l1 * cr1 + ts1;
#pragma unroll
        for (int nt = 0; nt < 8; nt++) {
            o[nt][0] *= cr0; o[nt][1] *= cr0;
            o[nt][2] *= cr1; o[nt][3] *= cr1;
        }

#pragma unroll
        for (int kc = 0; kc < 4; kc++) {
            uint32_t pf[4];
            pf[0] = packh(s[2*kc][0],   s[2*kc][1]);
            pf[1] = packh(s[2*kc][2],   s[2*kc][3]);
            pf[2] = packh(s[2*kc+1][0], s[2*kc+1][1]);
            pf[3] = packh(s[2*kc+1][2], s[2*kc+1][3]);
#pragma unroll
            for (int p = 0; p < 4; p++) {
                uint32_t vb[4];
                uint32_t ra = (uint32_t)((p * 16 + lrow) * KSTR) * 4 + kc * 32 + lseg;
                ldx4(vb, sv + ra);
                mma_f16(o[2*p],   pf, vb[0], vb[2]);
                mma_f16(o[2*p+1], pf, vb[1], vb[3]);
            }
        }
    }

    const float inv0 = 1.f / l0, inv1 = 1.f / l1;
    uint32_t* A0h = g_Ah + ((size_t)b * 2048 + t0 + lr) * 512 + h * 32;
    uint32_t* A0l = g_Al + ((size_t)b * 2048 + t0 + lr) * 512 + h * 32;
#pragma unroll
    for (int nt = 0; nt < 8; nt++) {
        const int j = nt * 4 + lc;
        uint32_t hh, ll;
        split2h(o[nt][0] * inv0, o[nt][1] * inv0, hh, ll);
        A0h[j] = hh; A0l[j] = ll;
        split2h(o[nt][2] * inv1, o[nt][3] * inv1, hh, ll);
        A0h[8 * 512 + j] = hh; A0l[8 * 512 + j] = ll;
    }
}

extern "C" void kernel_launch(void* const* d_in, const int* in_sizes, int n_in,
                              void* d_out, int out_size)
{
    const float* query = (const float*)d_in[0];
    const float* key   = (const float*)d_in[1];
    const float* value = (const float*)d_in[2];
    const unsigned char* mask = (const unsigned char*)d_in[3];
    const float* Wq = (const float*)d_in[4];
    const float* Wk = (const float*)d_in[5];
    const float* Wv = (const float*)d_in[6];
    const float* Wo = (const float*)d_in[7];

    const int SMEM_GEMM = 2 * STW2 * 4;   // 61440 B
    cudaFuncSetAttribute(gemm_qkv,   cudaFuncAttributeMaxDynamicSharedMemorySize, SMEM_GEMM);
    cudaFuncSetAttribute(gemm_oproj, cudaFuncAttributeMaxDynamicSharedMemorySize, SMEM_GEMM);

    zero_flag<<<1, 1>>>();
    mask_scan<<<256, 256>>>((const uint4*)mask, (B_ * T_ * T_) / 16);

    pack_all<<<2048, 256>>>(query, key, value, Wq, Wk, Wv, Wo);

    dim3 gq(24, 32);
    gemm_qkv<<<gq, 256, SMEM_GEMM>>>();

    dim3 gv(32, 32);
    v_pack<<<gv, 128>>>();

    dim3 ga(T_ / 64, B_ * H_);
    flash_attn7<<<ga, 128>>>(mask);

    dim3 go(8, 32);
    gemm_oproj<<<go, 256, SMEM_GEMM>>>((float*)d_out);
}

// round 15
// speedup vs baseline: 1.9882x; 1.0703x over previous
#include <cuda_runtime.h>
#include <cuda_fp16.h>
#include <cstdint>
#include <math.h>

#define B_  2
#define T_  2048
#define D_  1024
#define H_  16
#define DH  64

// ------------------------- scratch globals -------------------------
__device__ uint32_t g_qp[4096*512], g_kp[4096*512];
__device__ uint32_t g_Wqp[1024*512], g_Wkp[1024*512];
__device__ uint32_t g_vh[4096*512], g_vl[4096*512];
__device__ uint32_t g_Wvp[1024*512];
__device__ uint32_t g_Wop[1024*512];
__device__ uint32_t g_Qp[B_*H_*T_*32];
__device__ uint32_t g_Kp[B_*H_*T_*32];
__device__ float    g_V [B_*H_*T_*DH];
__device__ uint32_t g_Vp[(size_t)B_*H_*DH*1024];
__device__ uint32_t g_Ah[(size_t)4096*512], g_Al[(size_t)4096*512];
__device__ int      g_mask_any;

// ------------------------- helpers -------------------------
__device__ __forceinline__ uint32_t packh(float x, float y) {
    uint32_t r; asm("cvt.rn.f16x2.f32 %0, %1, %2;" : "=r"(r) : "f"(y), "f"(x)); return r;
}
__device__ __forceinline__ void split2h(float x, float y, uint32_t& h, uint32_t& l) {
    h = packh(x, y);
    __half2 hv = *reinterpret_cast<__half2*>(&h);
    l = packh(x - __half2float(hv.x), y - __half2float(hv.y));
}
__device__ __forceinline__ void mma_f16(float* d, const uint32_t* a, uint32_t b0, uint32_t b1) {
    asm volatile("mma.sync.aligned.m16n8k16.row.col.f32.f16.f16.f32 "
        "{%0,%1,%2,%3}, {%4,%5,%6,%7}, {%8,%9}, {%0,%1,%2,%3};"
        : "+f"(d[0]), "+f"(d[1]), "+f"(d[2]), "+f"(d[3])
        : "r"(a[0]), "r"(a[1]), "r"(a[2]), "r"(a[3]), "r"(b0), "r"(b1));
}
__device__ __forceinline__ void ldx4(uint32_t* r, uint32_t addr) {
    asm volatile("ldmatrix.sync.aligned.m8n8.x4.shared.b16 {%0,%1,%2,%3}, [%4];"
        : "=r"(r[0]), "=r"(r[1]), "=r"(r[2]), "=r"(r[3]) : "r"(addr));
}
__device__ __forceinline__ float ex2(float x) {
    float y; asm("ex2.approx.f32 %0, %1;" : "=f"(y) : "f"(x)); return y;
}
__device__ __forceinline__ uint32_t s2u(const void* p) {
    return (uint32_t)__cvta_generic_to_shared(p);
}
#define CP16(d, s) asm volatile("cp.async.cg.shared.global [%0], [%1], 16;" :: "r"(d), "l"(s))
#define CP_COMMIT  asm volatile("cp.async.commit_group;" ::: "memory")
#define CP_WAIT1   asm volatile("cp.async.wait_group 1;" ::: "memory")
#define CP_WAIT0   asm volatile("cp.async.wait_group 0;" ::: "memory")

// ------------------------- prep kernels -------------------------
__global__ void zero_flag() { g_mask_any = 0; }
__global__ __launch_bounds__(256) void mask_scan(const uint4* __restrict__ m, int n4)
{
    uint32_t acc = 0;
    for (int i = blockIdx.x * 256 + threadIdx.x; i < n4; i += gridDim.x * 256) {
        uint4 v = m[i];
        acc |= v.x | v.y | v.z | v.w;
    }
    acc |= __shfl_xor_sync(0xffffffff, acc, 16);
    acc |= __shfl_xor_sync(0xffffffff, acc, 8);
    acc |= __shfl_xor_sync(0xffffffff, acc, 4);
    acc |= __shfl_xor_sync(0xffffffff, acc, 2);
    acc |= __shfl_xor_sync(0xffffffff, acc, 1);
    if ((threadIdx.x & 31) == 0 && acc) atomicOr(&g_mask_any, 1);
}

__global__ __launch_bounds__(256) void pack_all(
    const float* q, const float* k, const float* v,
    const float* Wq, const float* Wk, const float* Wv, const float* Wo)
{
    const size_t NI = 4096 * 512, NW = 1024 * 512;
    size_t gid = (size_t)blockIdx.x * 256 + threadIdx.x;
    const size_t stride = (size_t)gridDim.x * 256;
    const size_t total = 3 * NI + 4 * NW;
    for (size_t i = gid; i < total; i += stride) {
        if (i < NI) {
            float2 vv = ((const float2*)q)[i];
            g_qp[i] = packh(vv.x, vv.y);
        } else if (i < 2*NI) {
            size_t off = i - NI;
            float2 vv = ((const float2*)k)[off];
            g_kp[off] = packh(vv.x, vv.y);
        } else if (i < 3*NI) {
            size_t off = i - 2*NI;
            float2 vv = ((const float2*)v)[off];
            uint32_t h, l; split2h(vv.x, vv.y, h, l);
            g_vh[off] = h; g_vl[off] = l;
        } else if (i < 3*NI+NW) {
            size_t off = i - 3*NI;
            float2 vv = ((const float2*)Wq)[off];
            g_Wqp[off] = packh(vv.x, vv.y);
        } else if (i < 3*NI+2*NW) {
            size_t off = i - 3*NI - NW;
            float2 vv = ((const float2*)Wk)[off];
            g_Wkp[off] = packh(vv.x, vv.y);
        } else if (i < 3*NI+3*NW) {
            size_t off = i - 3*NI - 2*NW;
            float2 vv = ((const float2*)Wv)[off];
            g_Wvp[off] = packh(vv.x, vv.y);
        } else {
            size_t off = i - 3*NI - 3*NW;
            float2 vv = ((const float2*)Wo)[off];
            g_Wop[off] = packh(vv.x, vv.y);
        }
    }
}

__global__ __launch_bounds__(128) void v_pack()
{
    __shared__ float tile[64][65];
    const int tid = threadIdx.x;
    const int bh = blockIdx.y, kt = blockIdx.x * 64;
    const float* Vb = g_V + ((size_t)bh * 2048 + kt) * 64;
#pragma unroll
    for (int i = 0; i < 16; i++) {
        int idx = tid + i * 128;
        int r = idx >> 5, dp = idx & 31;
        float2 v = ((const float2*)Vb)[r * 32 + dp];
        tile[r][dp * 2] = v.x; tile[r][dp * 2 + 1] = v.y;
    }
    __syncthreads();
#pragma unroll
    for (int i = 0; i < 16; i++) {
        int idx = tid + i * 128;
        int d = idx >> 5, kp = idx & 31;
        g_Vp[((size_t)bh * 64 + d) * 1024 + (kt >> 1) + kp] =
            packh(tile[2 * kp][d], tile[2 * kp + 1][d]);
    }
}

// ------------------------- GEMM mainloops: K_tile = 64 -------------------------
#define KW   36                    // words per 32-word row (conflict-free pad)
#define PLW2 (128 * KW)            // words per plane (18KB)
#define STWH (2 * PLW2)            // Q/K stage (A, B)
#define STW2 (3 * PLW2)            // V/O stage (Ah, Al, B)

// fp16 single-term (Q / K projections), K_tile=64, 16 iters
__device__ __forceinline__ void gemm_mainloop_h(
    const uint32_t* __restrict__ A, const uint32_t* __restrict__ B,
    int bm, int bn, uint32_t* sm, float acc[4][4][4],
    int wm, int wn, int lane, int tid)
{
    const uint32_t* gA = A + (size_t)bm * 512;
    const uint32_t* gB = B + (size_t)bn * 512;

#define HISSUE(it_) do { \
    uint32_t* st_ = sm + ((it_) & 1) * STWH; \
    _Pragma("unroll") \
    for (int u_ = 0; u_ < 4; u_++) { \
        const int idx_ = tid + u_ * 256; \
        const int row_ = idx_ >> 3, j4_ = (idx_ & 7) * 4; \
        const size_t go_ = (size_t)row_ * 512 + (it_) * 32 + j4_; \
        const int so_ = row_ * KW + j4_; \
        CP16(s2u(&st_[so_]),        &gA[go_]); \
        CP16(s2u(&st_[PLW2 + so_]), &gB[go_]); \
    } } while(0)

    const uint32_t smb = s2u(sm);
    const int lrow = (lane & 7) + ((lane >> 3) & 1) * 8;
    const int lseg = (lane >> 4) * 16;

    HISSUE(0); CP_COMMIT;
    for (int it = 0; it < 16; ++it) {
        if (it < 15) { HISSUE(it + 1); CP_COMMIT; CP_WAIT1; }
        else CP_WAIT0;
        __syncthreads();
        const uint32_t stb = smb + ((it & 1) * STWH) * 4;
#pragma unroll
        for (int c = 0; c < 4; ++c) {
            uint32_t af[4][4];
#pragma unroll
            for (int mt = 0; mt < 4; ++mt) {
                uint32_t ra = stb + (uint32_t)((wm + mt * 16 + lrow) * KW) * 4 + c * 32 + lseg;
                ldx4(af[mt], ra);
            }
#pragma unroll
            for (int p = 0; p < 2; ++p) {
                uint32_t bb[4];
                uint32_t rb = stb + (uint32_t)PLW2 * 4
                            + (uint32_t)((wn + p * 16 + lrow) * KW) * 4 + c * 32 + lseg;
                ldx4(bb, rb);
#pragma unroll
                for (int mt = 0; mt < 4; ++mt) {
                    mma_f16(acc[mt][2*p],   af[mt], bb[0], bb[2]);
                    mma_f16(acc[mt][2*p+1], af[mt], bb[1], bb[3]);
                }
            }
        }
        __syncthreads();
    }
#undef HISSUE
}

// fp16 split-A 2-term (V / O projections), K_tile=64, 16 iters
__device__ __forceinline__ void gemm_mainloop_h2(
    const uint32_t* __restrict__ Ah, const uint32_t* __restrict__ Al,
    const uint32_t* __restrict__ B,
    int bm, int bn, uint32_t* sm, float acc[4][4][4],
    int wm, int wn, int lane, int tid)
{
    const uint32_t* gAh = Ah + (size_t)bm * 512;
    const uint32_t* gAl = Al + (size_t)bm * 512;
    const uint32_t* gB  = B  + (size_t)bn * 512;

#define H2ISSUE(it_) do { \
    uint32_t* st_ = sm + ((it_) & 1) * STW2; \
    _Pragma("unroll") \
    for (int u_ = 0; u_ < 4; u_++) { \
        const int idx_ = tid + u_ * 256; \
        const int row_ = idx_ >> 3, j4_ = (idx_ & 7) * 4; \
        const size_t go_ = (size_t)row_ * 512 + (it_) * 32 + j4_; \
        const int so_ = row_ * KW + j4_; \
        CP16(s2u(&st_[so_]),            &gAh[go_]); \
        CP16(s2u(&st_[PLW2 + so_]),     &gAl[go_]); \
        CP16(s2u(&st_[2*PLW2 + so_]),   &gB[go_]); \
    } } while(0)

    const uint32_t smb = s2u(sm);
    const int lrow = (lane & 7) + ((lane >> 3) & 1) * 8;
    const int lseg = (lane >> 4) * 16;

    H2ISSUE(0); CP_COMMIT;
    for (int it = 0; it < 16; ++it) {
        if (it < 15) { H2ISSUE(it + 1); CP_COMMIT; CP_WAIT1; }
        else CP_WAIT0;
        __syncthreads();
        const uint32_t stb = smb + ((it & 1) * STW2) * 4;
#pragma unroll
        for (int c = 0; c < 4; ++c) {
            uint32_t ah[4][4], al[4][4];
#pragma unroll
            for (int mt = 0; mt < 4; ++mt) {
                uint32_t ra = stb + (uint32_t)((wm + mt * 16 + lrow) * KW) * 4 + c * 32 + lseg;
                ldx4(ah[mt], ra);
                ldx4(al[mt], ra + PLW2 * 4);
            }
#pragma unroll
            for (int p = 0; p < 2; ++p) {
                uint32_t bb[4];
                uint32_t rb = stb + (uint32_t)(2 * PLW2) * 4
                            + (uint32_t)((wn + p * 16 + lrow) * KW) * 4 + c * 32 + lseg;
                ldx4(bb, rb);
#pragma unroll
                for (int mt = 0; mt < 4; ++mt) {
                    mma_f16(acc[mt][2*p],   ah[mt], bb[0], bb[2]);
                    mma_f16(acc[mt][2*p+1], ah[mt], bb[1], bb[3]);
                }
#pragma unroll
                for (int mt = 0; mt < 4; ++mt) {
                    mma_f16(acc[mt][2*p],   al[mt], bb[0], bb[2]);
                    mma_f16(acc[mt][2*p+1], al[mt], bb[1], bb[3]);
                }
            }
        }
        __syncthreads();
    }
#undef H2ISSUE
}

// ------------------------- fused QKV projection -------------------------
#define QSCALE 0.18033688f   // (1/8) * log2(e)
__global__ __launch_bounds__(256, 2) void gemm_qkv()
{
    extern __shared__ __align__(16) uint32_t smw[];
    const int which = blockIdx.x >> 3;
    const int bn = (blockIdx.x & 7) * 128;
    const int bm = blockIdx.y * 128;

    const int tid = threadIdx.x;
    const int wid = tid >> 5, lane = tid & 31;
    const int wm = (wid & 1) * 64, wn = (wid >> 1) * 32;
    const int lr = lane >> 2, lc = lane & 3;

    float acc[4][4][4];
#pragma unroll
    for (int mt = 0; mt < 4; mt++)
#pragma unroll
        for (int nt = 0; nt < 4; nt++)
#pragma unroll
            for (int i = 0; i < 4; i++) acc[mt][nt][i] = 0.f;

    if (which < 2) {
        const uint32_t* A = which == 0 ? g_qp : g_kp;
        const uint32_t* B = which == 0 ? g_Wqp : g_Wkp;
        gemm_mainloop_h(A, B, bm, bn, smw, acc, wm, wn, lane, tid);
        uint32_t* P = which == 0 ? g_Qp : g_Kp;
        const float sc = which == 0 ? QSCALE : 1.0f;
#pragma unroll
        for (int mt = 0; mt < 4; ++mt)
#pragma unroll
            for (int nt = 0; nt < 4; ++nt) {
                const int row  = bm + wm + mt * 16 + lr;
                const int col0 = bn + wn + nt * 8 + lc * 2;
                const int hh = col0 >> 6, j = (col0 & 63) >> 1;
                const float* d = acc[mt][nt];
                int b = row >> 11, t = row & 2047;
                P[((size_t)(b * 16 + hh) * 2048 + t) * 32 + j] = packh(d[0] * sc, d[1] * sc);
                b = (row + 8) >> 11; t = (row + 8) & 2047;
                P[((size_t)(b * 16 + hh) * 2048 + t) * 32 + j] = packh(d[2] * sc, d[3] * sc);
            }
    } else {
        gemm_mainloop_h2(g_vh, g_vl, g_Wvp, bm, bn, smw, acc, wm, wn, lane, tid);
#pragma unroll
        for (int mt = 0; mt < 4; ++mt)
#pragma unroll
            for (int nt = 0; nt < 4; ++nt) {
                const int row  = bm + wm + mt * 16 + lr;
                const int col0 = bn + wn + nt * 8 + lc * 2;
                const int hh = col0 >> 6, dd = col0 & 63;
                const float* d = acc[mt][nt];
                int b = row >> 11, t = row & 2047;
                *(float2*)(g_V + (((size_t)(b * 16 + hh) * 2048 + t) * 64 + dd)) = make_float2(d[0], d[1]);
                b = (row + 8) >> 11; t = (row + 8) & 2047;
                *(float2*)(g_V + (((size_t)(b * 16 + hh) * 2048 + t) * 64 + dd)) = make_float2(d[2], d[3]);
            }
    }
}

// ------------------------- output projection -------------------------
__global__ __launch_bounds__(256, 2) void gemm_oproj(float* __restrict__ C)
{
    extern __shared__ __align__(16) uint32_t smw[];
    const int bn = blockIdx.x * 128;
    const int bm = blockIdx.y * 128;
    const int tid = threadIdx.x;
    const int wid = tid >> 5, lane = tid & 31;
    const int wm = (wid & 1) * 64, wn = (wid >> 1) * 32;
    const int lr = lane >> 2, lc = lane & 3;

    float acc[4][4][4];
#pragma unroll
    for (int mt = 0; mt < 4; mt++)
#pragma unroll
        for (int nt = 0; nt < 4; nt++)
#pragma unroll
            for (int i = 0; i < 4; i++) acc[mt][nt][i] = 0.f;

    gemm_mainloop_h2(g_Ah, g_Al, g_Wop, bm, bn, smw, acc, wm, wn, lane, tid);

#pragma unroll
    for (int mt = 0; mt < 4; ++mt)
#pragma unroll
        for (int nt = 0; nt < 4; ++nt) {
            const int row  = bm + wm + mt * 16 + lr;
            const int col0 = bn + wn + nt * 8 + lc * 2;
            const float* d = acc[mt][nt];
            *(float2*)(C + (size_t)row * 1024 + col0)       = make_float2(d[0], d[1]);
            *(float2*)(C + (size_t)(row + 8) * 1024 + col0) = make_float2(d[2], d[3]);
        }
}

// ------------------------- flash attention: fp16 single-term (unchanged) -------------------------
#define KSTR 36
__global__ __launch_bounds__(128, 4) void flash_attn7(
    const unsigned char* __restrict__ mask)
{
    __shared__ __align__(16) uint32_t SK[64*KSTR], SV[64*KSTR];

    const int tid = threadIdx.x;
    const int w = tid >> 5, lane = tid & 31;
    const int lr = lane >> 2, lc = lane & 3;
    const int bh = blockIdx.y, b = bh >> 4, h = bh & 15;
    const int q0 = blockIdx.x * 64;
    const int t0 = q0 + w * 16;
    const bool anymask = (g_mask_any != 0);

    uint32_t qf[4][4];
    {
        const uint32_t* q0p = g_Qp + ((size_t)bh * 2048 + t0 + lr) * 32;
        const uint32_t* q1p = q0p + 8 * 32;
#pragma unroll
        for (int c = 0; c < 4; c++) {
            const int j = c * 8 + lc;
            qf[c][0] = q0p[j];     qf[c][1] = q1p[j];
            qf[c][2] = q0p[j + 4]; qf[c][3] = q1p[j + 4];
        }
    }

    float m0 = -1e30f, m1 = -1e30f, l0 = 0.f, l1 = 0.f;
    float o[8][4];
#pragma unroll
    for (int nt = 0; nt < 8; nt++)
#pragma unroll
        for (int i = 0; i < 4; i++) o[nt][i] = 0.f;

    const unsigned char* mrow0 = mask + ((size_t)b * 2048 + t0 + lr) * 2048;
    const unsigned char* mrow1 = mrow0 + 8 * 2048;

    const uint32_t sk = s2u(SK), sv = s2u(SV);
    const int lrow = (lane & 7) + ((lane >> 3) & 1) * 8;
    const int lseg = (lane >> 4) * 16;

    for (int kt = 0; kt < 2048; kt += 64) {
        __syncthreads();
        {
            const uint32_t* KP = g_Kp + ((size_t)bh * 2048 + kt) * 32;
            const uint32_t* VP = g_Vp + (size_t)bh * 64 * 1024 + (kt >> 1);
#pragma unroll
            for (int i = 0; i < 4; i++) {
                int idx = tid + i * 128;
                int r = idx >> 3, j4 = (idx & 7) * 4;
                *(uint4*)&SK[r * KSTR + j4] = *(const uint4*)&KP[r * 32 + j4];
                *(uint4*)&SV[r * KSTR + j4] = *(const uint4*)&VP[(size_t)r * 1024 + j4];
            }
        }
        __syncthreads();

        float s[8][4];
#pragma unroll
        for (int nt = 0; nt < 8; nt++)
#pragma unroll
            for (int i = 0; i < 4; i++) s[nt][i] = 0.f;
#pragma unroll
        for (int c = 0; c < 4; c++) {
#pragma unroll
            for (int p = 0; p < 4; p++) {
                uint32_t kb[4];
                uint32_t ra = (uint32_t)((p * 16 + lrow) * KSTR) * 4 + c * 32 + lseg;
                ldx4(kb, sk + ra);
                mma_f16(s[2*p],   qf[c], kb[0], kb[2]);
                mma_f16(s[2*p+1], qf[c], kb[1], kb[3]);
            }
        }

        if (anymask) {
#pragma unroll
            for (int nt = 0; nt < 8; nt++) {
                const int cc = kt + nt * 8 + lc * 2;
                if (mrow0[cc])     s[nt][0] = -1e30f;
                if (mrow0[cc + 1]) s[nt][1] = -1e30f;
                if (mrow1[cc])     s[nt][2] = -1e30f;
                if (mrow1[cc + 1]) s[nt][3] = -1e30f;
            }
        }

        float tm0 = -1e30f, tm1 = -1e30f;
#pragma unroll
        for (int nt = 0; nt < 8; nt++) {
            tm0 = fmaxf(tm0, fmaxf(s[nt][0], s[nt][1]));
            tm1 = fmaxf(tm1, fmaxf(s[nt][2], s[nt][3]));
        }
        tm0 = fmaxf(tm0, __shfl_xor_sync(0xffffffff, tm0, 1));
        tm0 = fmaxf(tm0, __shfl_xor_sync(0xffffffff, tm0, 2));
        tm1 = fmaxf(tm1, __shfl_xor_sync(0xffffffff, tm1, 1));
        tm1 = fmaxf(tm1, __shfl_xor_sync(0xffffffff, tm1, 2));
        float mn0 = fmaxf(m0, tm0), mn1 = fmaxf(m1, tm1);
        float cr0 = ex2(m0 - mn0), cr1 = ex2(m1 - mn1);
        m0 = mn0; m1 = mn1;
        float ts0 = 0.f, ts1 = 0.f;
#pragma unroll
        for (int nt = 0; nt < 8; nt++) {
            s[nt][0] = ex2(s[nt][0] - mn0);
            s[nt][1] = ex2(s[nt][1] - mn0);
            s[nt][2] = ex2(s[nt][2] - mn1);
            s[nt][3] = ex2(s[nt][3] - mn1);
            ts0 += s[nt][0] + s[nt][1];
            ts1 += s[nt][2] + s[nt][3];
        }
        ts0 += __shfl_xor_sync(0xffffffff, ts0, 1);
        ts0 += __shfl_xor_sync(0xffffffff, ts0, 2);
        ts1 += __shfl_xor_sync(0xffffffff, ts1, 1);
        ts1 += __shfl_xor_sync(0xffffffff, ts1, 2);
        l0 = l0 * cr0 + ts0;
        l1 = l1 * cr1 + ts1;
#pragma unroll
        for (int nt = 0; nt < 8; nt++) {
            o[nt][0] *= cr0; o[nt][1] *= cr0;
            o[nt][2] *= cr1; o[nt][3] *= cr1;
        }

#pragma unroll
        for (int kc = 0; kc < 4; kc++) {
            uint32_t pf[4];
            pf[0] = packh(s[2*kc][0],   s[2*kc][1]);
            pf[1] = packh(s[2*kc][2],   s[2*kc][3]);
            pf[2] = packh(s[2*kc+1][0], s[2*kc+1][1]);
            pf[3] = packh(s[2*kc+1][2], s[2*kc+1][3]);
#pragma unroll
            for (int p = 0; p < 4; p++) {
                uint32_t vb[4];
                uint32_t ra = (uint32_t)((p * 16 + lrow) * KSTR) * 4 + kc * 32 + lseg;
                ldx4(vb, sv + ra);
                mma_f16(o[2*p],   pf, vb[0], vb[2]);
                mma_f16(o[2*p+1], pf, vb[1], vb[3]);
            }
        }
    }

    const float inv0 = 1.f / l0, inv1 = 1.f / l1;
    uint32_t* A0h = g_Ah + ((size_t)b * 2048 + t0 + lr) * 512 + h * 32;
    uint32_t* A0l = g_Al + ((size_t)b * 2048 + t0 + lr) * 512 + h * 32;
#pragma unroll
    for (int nt = 0; nt < 8; nt++) {
        const int j = nt * 4 + lc;
        uint32_t hh, ll;
        split2h(o[nt][0] * inv0, o[nt][1] * inv0, hh, ll);
        A0h[j] = hh; A0l[j] = ll;
        split2h(o[nt][2] * inv1, o[nt][3] * inv1, hh, ll);
        A0h[8 * 512 + j] = hh; A0l[8 * 512 + j] = ll;
    }
}

extern "C" void kernel_launch(void* const* d_in, const int* in_sizes, int n_in,
                              void* d_out, int out_size)
{
    const float* query = (const float*)d_in[0];
    const float* key   = (const float*)d_in[1];
    const float* value = (const float*)d_in[2];
    const unsigned char* mask = (const unsigned char*)d_in[3];
    const float* Wq = (const float*)d_in[4];
    const float* Wk = (const float*)d_in[5];
    const float* Wv = (const float*)d_in[6];
    const float* Wo = (const float*)d_in[7];

    const int SMEM_GEMM = 2 * STW2 * 4;   // 110592 B (2 stages x 3 planes x 18KB)
    cudaFuncSetAttribute(gemm_qkv,   cudaFuncAttributeMaxDynamicSharedMemorySize, SMEM_GEMM);
    cudaFuncSetAttribute(gemm_oproj, cudaFuncAttributeMaxDynamicSharedMemorySize, SMEM_GEMM);

    zero_flag<<<1, 1>>>();
    mask_scan<<<256, 256>>>((const uint4*)mask, (B_ * T_ * T_) / 16);

    pack_all<<<2048, 256>>>(query, key, value, Wq, Wk, Wv, Wo);

    dim3 gq(24, 32);
    gemm_qkv<<<gq, 256, SMEM_GEMM>>>();

    dim3 gv(32, 32);
    v_pack<<<gv, 128>>>();

    dim3 ga(T_ / 64, B_ * H_);
    flash_attn7<<<ga, 128>>>(mask);

    dim3 go(8, 32);
    gemm_oproj<<<go, 256, SMEM_GEMM>>>((float*)d_out);
}

// round 16
// speedup vs baseline: 2.0585x; 1.0354x over previous
#include <cuda_runtime.h>
#include <cuda_fp16.h>
#include <cstdint>
#include <math.h>

#define B_  2
#define T_  2048
#define D_  1024
#define H_  16
#define DH  64

// ------------------------- scratch globals -------------------------
__device__ uint32_t g_qp[4096*512], g_kp[4096*512];
__device__ uint32_t g_Wqp[1024*512], g_Wkp[1024*512];
__device__ uint32_t g_vh[4096*512], g_vl[4096*512];
__device__ uint32_t g_Wvp[1024*512];
__device__ uint32_t g_Wop[1024*512];
__device__ uint32_t g_Qp[B_*H_*T_*32];
__device__ uint32_t g_Kp[B_*H_*T_*32];
__device__ float    g_V [B_*H_*T_*DH];
__device__ uint32_t g_Vp[(size_t)B_*H_*DH*1024];
__device__ uint32_t g_Ah[(size_t)4096*512], g_Al[(size_t)4096*512];
__device__ int      g_mask_any;

// ------------------------- helpers -------------------------
__device__ __forceinline__ uint32_t packh(float x, float y) {
    uint32_t r; asm("cvt.rn.f16x2.f32 %0, %1, %2;" : "=r"(r) : "f"(y), "f"(x)); return r;
}
__device__ __forceinline__ void split2h(float x, float y, uint32_t& h, uint32_t& l) {
    h = packh(x, y);
    __half2 hv = *reinterpret_cast<__half2*>(&h);
    l = packh(x - __half2float(hv.x), y - __half2float(hv.y));
}
__device__ __forceinline__ void mma_f16(float* d, const uint32_t* a, uint32_t b0, uint32_t b1) {
    asm volatile("mma.sync.aligned.m16n8k16.row.col.f32.f16.f16.f32 "
        "{%0,%1,%2,%3}, {%4,%5,%6,%7}, {%8,%9}, {%0,%1,%2,%3};"
        : "+f"(d[0]), "+f"(d[1]), "+f"(d[2]), "+f"(d[3])
        : "r"(a[0]), "r"(a[1]), "r"(a[2]), "r"(a[3]), "r"(b0), "r"(b1));
}
__device__ __forceinline__ void ldx4(uint32_t* r, uint32_t addr) {
    asm volatile("ldmatrix.sync.aligned.m8n8.x4.shared.b16 {%0,%1,%2,%3}, [%4];"
        : "=r"(r[0]), "=r"(r[1]), "=r"(r[2]), "=r"(r[3]) : "r"(addr));
}
__device__ __forceinline__ float ex2(float x) {
    float y; asm("ex2.approx.f32 %0, %1;" : "=f"(y) : "f"(x)); return y;
}
__device__ __forceinline__ uint32_t s2u(const void* p) {
    return (uint32_t)__cvta_generic_to_shared(p);
}
#define CP16(d, s) asm volatile("cp.async.cg.shared.global [%0], [%1], 16;" :: "r"(d), "l"(s))
#define CP_COMMIT  asm volatile("cp.async.commit_group;" ::: "memory")
#define CP_WAIT1   asm volatile("cp.async.wait_group 1;" ::: "memory")
#define CP_WAIT0   asm volatile("cp.async.wait_group 0;" ::: "memory")

// ------------------------- prep kernels -------------------------
__global__ void zero_flag() { g_mask_any = 0; }
__global__ __launch_bounds__(256) void mask_scan(const uint4* __restrict__ m, int n4)
{
    uint32_t acc = 0;
    for (int i = blockIdx.x * 256 + threadIdx.x; i < n4; i += gridDim.x * 256) {
        uint4 v = m[i];
        acc |= v.x | v.y | v.z | v.w;
    }
    acc |= __shfl_xor_sync(0xffffffff, acc, 16);
    acc |= __shfl_xor_sync(0xffffffff, acc, 8);
    acc |= __shfl_xor_sync(0xffffffff, acc, 4);
    acc |= __shfl_xor_sync(0xffffffff, acc, 2);
    acc |= __shfl_xor_sync(0xffffffff, acc, 1);
    if ((threadIdx.x & 31) == 0 && acc) atomicOr(&g_mask_any, 1);
}

__global__ __launch_bounds__(256) void pack_all(
    const float* q, const float* k, const float* v,
    const float* Wq, const float* Wk, const float* Wv, const float* Wo)
{
    const size_t NI = 4096 * 512, NW = 1024 * 512;
    size_t gid = (size_t)blockIdx.x * 256 + threadIdx.x;
    const size_t stride = (size_t)gridDim.x * 256;
    const size_t total = 3 * NI + 4 * NW;
    for (size_t i = gid; i < total; i += stride) {
        if (i < NI) {
            float2 vv = ((const float2*)q)[i];
            g_qp[i] = packh(vv.x, vv.y);
        } else if (i < 2*NI) {
            size_t off = i - NI;
            float2 vv = ((const float2*)k)[off];
            g_kp[off] = packh(vv.x, vv.y);
        } else if (i < 3*NI) {
            size_t off = i - 2*NI;
            float2 vv = ((const float2*)v)[off];
            uint32_t h, l; split2h(vv.x, vv.y, h, l);
            g_vh[off] = h; g_vl[off] = l;
        } else if (i < 3*NI+NW) {
            size_t off = i - 3*NI;
            float2 vv = ((const float2*)Wq)[off];
            g_Wqp[off] = packh(vv.x, vv.y);
        } else if (i < 3*NI+2*NW) {
            size_t off = i - 3*NI - NW;
            float2 vv = ((const float2*)Wk)[off];
            g_Wkp[off] = packh(vv.x, vv.y);
        } else if (i < 3*NI+3*NW) {
            size_t off = i - 3*NI - 2*NW;
            float2 vv = ((const float2*)Wv)[off];
            g_Wvp[off] = packh(vv.x, vv.y);
        } else {
            size_t off = i - 3*NI - 3*NW;
            float2 vv = ((const float2*)Wo)[off];
            g_Wop[off] = packh(vv.x, vv.y);
        }
    }
}

__global__ __launch_bounds__(128) void v_pack()
{
    __shared__ float tile[64][65];
    const int tid = threadIdx.x;
    const int bh = blockIdx.y, kt = blockIdx.x * 64;
    const float* Vb = g_V + ((size_t)bh * 2048 + kt) * 64;
#pragma unroll
    for (int i = 0; i < 16; i++) {
        int idx = tid + i * 128;
        int r = idx >> 5, dp = idx & 31;
        float2 v = ((const float2*)Vb)[r * 32 + dp];
        tile[r][dp * 2] = v.x; tile[r][dp * 2 + 1] = v.y;
    }
    __syncthreads();
#pragma unroll
    for (int i = 0; i < 16; i++) {
        int idx = tid + i * 128;
        int d = idx >> 5, kp = idx & 31;
        g_Vp[((size_t)bh * 64 + d) * 1024 + (kt >> 1) + kp] =
            packh(tile[2 * kp][d], tile[2 * kp + 1][d]);
    }
}

// ------------------------- GEMM mainloops: K_tile = 64 (R14 winner) -------------------------
#define KW   36
#define PLW2 (128 * KW)
#define STWH (2 * PLW2)
#define STW2 (3 * PLW2)

__device__ __forceinline__ void gemm_mainloop_h(
    const uint32_t* __restrict__ A, const uint32_t* __restrict__ B,
    int bm, int bn, uint32_t* sm, float acc[4][4][4],
    int wm, int wn, int lane, int tid)
{
    const uint32_t* gA = A + (size_t)bm * 512;
    const uint32_t* gB = B + (size_t)bn * 512;

#define HISSUE(it_) do { \
    uint32_t* st_ = sm + ((it_) & 1) * STWH; \
    _Pragma("unroll") \
    for (int u_ = 0; u_ < 4; u_++) { \
        const int idx_ = tid + u_ * 256; \
        const int row_ = idx_ >> 3, j4_ = (idx_ & 7) * 4; \
        const size_t go_ = (size_t)row_ * 512 + (it_) * 32 + j4_; \
        const int so_ = row_ * KW + j4_; \
        CP16(s2u(&st_[so_]),        &gA[go_]); \
        CP16(s2u(&st_[PLW2 + so_]), &gB[go_]); \
    } } while(0)

    const uint32_t smb = s2u(sm);
    const int lrow = (lane & 7) + ((lane >> 3) & 1) * 8;
    const int lseg = (lane >> 4) * 16;

    HISSUE(0); CP_COMMIT;
    for (int it = 0; it < 16; ++it) {
        if (it < 15) { HISSUE(it + 1); CP_COMMIT; CP_WAIT1; }
        else CP_WAIT0;
        __syncthreads();
        const uint32_t stb = smb + ((it & 1) * STWH) * 4;
#pragma unroll
        for (int c = 0; c < 4; ++c) {
            uint32_t af[4][4];
#pragma unroll
            for (int mt = 0; mt < 4; ++mt) {
                uint32_t ra = stb + (uint32_t)((wm + mt * 16 + lrow) * KW) * 4 + c * 32 + lseg;
                ldx4(af[mt], ra);
            }
#pragma unroll
            for (int p = 0; p < 2; ++p) {
                uint32_t bb[4];
                uint32_t rb = stb + (uint32_t)PLW2 * 4
                            + (uint32_t)((wn + p * 16 + lrow) * KW) * 4 + c * 32 + lseg;
                ldx4(bb, rb);
#pragma unroll
                for (int mt = 0; mt < 4; ++mt) {
                    mma_f16(acc[mt][2*p],   af[mt], bb[0], bb[2]);
                    mma_f16(acc[mt][2*p+1], af[mt], bb[1], bb[3]);
                }
            }
        }
        __syncthreads();
    }
#undef HISSUE
}

__device__ __forceinline__ void gemm_mainloop_h2(
    const uint32_t* __restrict__ Ah, const uint32_t* __restrict__ Al,
    const uint32_t* __restrict__ B,
    int bm, int bn, uint32_t* sm, float acc[4][4][4],
    int wm, int wn, int lane, int tid)
{
    const uint32_t* gAh = Ah + (size_t)bm * 512;
    const uint32_t* gAl = Al + (size_t)bm * 512;
    const uint32_t* gB  = B  + (size_t)bn * 512;

#define H2ISSUE(it_) do { \
    uint32_t* st_ = sm + ((it_) & 1) * STW2; \
    _Pragma("unroll") \
    for (int u_ = 0; u_ < 4; u_++) { \
        const int idx_ = tid + u_ * 256; \
        const int row_ = idx_ >> 3, j4_ = (idx_ & 7) * 4; \
        const size_t go_ = (size_t)row_ * 512 + (it_) * 32 + j4_; \
        const int so_ = row_ * KW + j4_; \
        CP16(s2u(&st_[so_]),            &gAh[go_]); \
        CP16(s2u(&st_[PLW2 + so_]),     &gAl[go_]); \
        CP16(s2u(&st_[2*PLW2 + so_]),   &gB[go_]); \
    } } while(0)

    const uint32_t smb = s2u(sm);
    const int lrow = (lane & 7) + ((lane >> 3) & 1) * 8;
    const int lseg = (lane >> 4) * 16;

    H2ISSUE(0); CP_COMMIT;
    for (int it = 0; it < 16; ++it) {
        if (it < 15) { H2ISSUE(it + 1); CP_COMMIT; CP_WAIT1; }
        else CP_WAIT0;
        __syncthreads();
        const uint32_t stb = smb + ((it & 1) * STW2) * 4;
#pragma unroll
        for (int c = 0; c < 4; ++c) {
            uint32_t ah[4][4], al[4][4];
#pragma unroll
            for (int mt = 0; mt < 4; ++mt) {
                uint32_t ra = stb + (uint32_t)((wm + mt * 16 + lrow) * KW) * 4 + c * 32 + lseg;
                ldx4(ah[mt], ra);
                ldx4(al[mt], ra + PLW2 * 4);
            }
#pragma unroll
            for (int p = 0; p < 2; ++p) {
                uint32_t bb[4];
                uint32_t rb = stb + (uint32_t)(2 * PLW2) * 4
                            + (uint32_t)((wn + p * 16 + lrow) * KW) * 4 + c * 32 + lseg;
                ldx4(bb, rb);
#pragma unroll
                for (int mt = 0; mt < 4; ++mt) {
                    mma_f16(acc[mt][2*p],   ah[mt], bb[0], bb[2]);
                    mma_f16(acc[mt][2*p+1], ah[mt], bb[1], bb[3]);
                }
#pragma unroll
                for (int mt = 0; mt < 4; ++mt) {
                    mma_f16(acc[mt][2*p],   al[mt], bb[0], bb[2]);
                    mma_f16(acc[mt][2*p+1], al[mt], bb[1], bb[3]);
                }
            }
        }
        __syncthreads();
    }
#undef H2ISSUE
}

// ------------------------- fused QKV projection -------------------------
#define QSCALE 0.18033688f
__global__ __launch_bounds__(256, 2) void gemm_qkv()
{
    extern __shared__ __align__(16) uint32_t smw[];
    const int which = blockIdx.x >> 3;
    const int bn = (blockIdx.x & 7) * 128;
    const int bm = blockIdx.y * 128;

    const int tid = threadIdx.x;
    const int wid = tid >> 5, lane = tid & 31;
    const int wm = (wid & 1) * 64, wn = (wid >> 1) * 32;
    const int lr = lane >> 2, lc = lane & 3;

    float acc[4][4][4];
#pragma unroll
    for (int mt = 0; mt < 4; mt++)
#pragma unroll
        for (int nt = 0; nt < 4; nt++)
#pragma unroll
            for (int i = 0; i < 4; i++) acc[mt][nt][i] = 0.f;

    if (which < 2) {
        const uint32_t* A = which == 0 ? g_qp : g_kp;
        const uint32_t* B = which == 0 ? g_Wqp : g_Wkp;
        gemm_mainloop_h(A, B, bm, bn, smw, acc, wm, wn, lane, tid);
        uint32_t* P = which == 0 ? g_Qp : g_Kp;
        const float sc = which == 0 ? QSCALE : 1.0f;
#pragma unroll
        for (int mt = 0; mt < 4; ++mt)
#pragma unroll
            for (int nt = 0; nt < 4; ++nt) {
                const int row  = bm + wm + mt * 16 + lr;
                const int col0 = bn + wn + nt * 8 + lc * 2;
                const int hh = col0 >> 6, j = (col0 & 63) >> 1;
                const float* d = acc[mt][nt];
                int b = row >> 11, t = row & 2047;
                P[((size_t)(b * 16 + hh) * 2048 + t) * 32 + j] = packh(d[0] * sc, d[1] * sc);
                b = (row + 8) >> 11; t = (row + 8) & 2047;
                P[((size_t)(b * 16 + hh) * 2048 + t) * 32 + j] = packh(d[2] * sc, d[3] * sc);
            }
    } else {
        gemm_mainloop_h2(g_vh, g_vl, g_Wvp, bm, bn, smw, acc, wm, wn, lane, tid);
#pragma unroll
        for (int mt = 0; mt < 4; ++mt)
#pragma unroll
            for (int nt = 0; nt < 4; ++nt) {
                const int row  = bm + wm + mt * 16 + lr;
                const int col0 = bn + wn + nt * 8 + lc * 2;
                const int hh = col0 >> 6, dd = col0 & 63;
                const float* d = acc[mt][nt];
                int b = row >> 11, t = row & 2047;
                *(float2*)(g_V + (((size_t)(b * 16 + hh) * 2048 + t) * 64 + dd)) = make_float2(d[0], d[1]);
                b = (row + 8) >> 11; t = (row + 8) & 2047;
                *(float2*)(g_V + (((size_t)(b * 16 + hh) * 2048 + t) * 64 + dd)) = make_float2(d[2], d[3]);
            }
    }
}

// ------------------------- output projection -------------------------
__global__ __launch_bounds__(256, 2) void gemm_oproj(float* __restrict__ C)
{
    extern __shared__ __align__(16) uint32_t smw[];
    const int bn = blockIdx.x * 128;
    const int bm = blockIdx.y * 128;
    const int tid = threadIdx.x;
    const int wid = tid >> 5, lane = tid & 31;
    const int wm = (wid & 1) * 64, wn = (wid >> 1) * 32;
    const int lr = lane >> 2, lc = lane & 3;

    float acc[4][4][4];
#pragma unroll
    for (int mt = 0; mt < 4; mt++)
#pragma unroll
        for (int nt = 0; nt < 4; nt++)
#pragma unroll
            for (int i = 0; i < 4; i++) acc[mt][nt][i] = 0.f;

    gemm_mainloop_h2(g_Ah, g_Al, g_Wop, bm, bn, smw, acc, wm, wn, lane, tid);

#pragma unroll
    for (int mt = 0; mt < 4; ++mt)
#pragma unroll
        for (int nt = 0; nt < 4; ++nt) {
            const int row  = bm + wm + mt * 16 + lr;
            const int col0 = bn + wn + nt * 8 + lc * 2;
            const float* d = acc[mt][nt];
            *(float2*)(C + (size_t)row * 1024 + col0)       = make_float2(d[0], d[1]);
            *(float2*)(C + (size_t)(row + 8) * 1024 + col0) = make_float2(d[2], d[3]);
        }
}

// ------------------------- flash attention: fp16, cp.async double-buffered -------------------------
#define KSTR 36
#define FPL (64 * KSTR)   // words per tile (K or V)
__global__ __launch_bounds__(128, 4) void flash_attn8(
    const unsigned char* __restrict__ mask)
{
    __shared__ __align__(16) uint32_t SK[2 * FPL], SV[2 * FPL];

    const int tid = threadIdx.x;
    const int w = tid >> 5, lane = tid & 31;
    const int lr = lane >> 2, lc = lane & 3;
    const int bh = blockIdx.y, b = bh >> 4, h = bh & 15;
    const int q0 = blockIdx.x * 64;
    const int t0 = q0 + w * 16;
    const bool anymask = (g_mask_any != 0);

    uint32_t qf[4][4];
    {
        const uint32_t* q0p = g_Qp + ((size_t)bh * 2048 + t0 + lr) * 32;
        const uint32_t* q1p = q0p + 8 * 32;
#pragma unroll
        for (int c = 0; c < 4; c++) {
            const int j = c * 8 + lc;
            qf[c][0] = q0p[j];     qf[c][1] = q1p[j];
            qf[c][2] = q0p[j + 4]; qf[c][3] = q1p[j + 4];
        }
    }

    float m0 = -1e30f, m1 = -1e30f, l0 = 0.f, l1 = 0.f;
    float o[8][4];
#pragma unroll
    for (int nt = 0; nt < 8; nt++)
#pragma unroll
        for (int i = 0; i < 4; i++) o[nt][i] = 0.f;

    const unsigned char* mrow0 = mask + ((size_t)b * 2048 + t0 + lr) * 2048;
    const unsigned char* mrow1 = mrow0 + 8 * 2048;

    const uint32_t sk = s2u(SK), sv = s2u(SV);
    const int lrow = (lane & 7) + ((lane >> 3) & 1) * 8;
    const int lseg = (lane >> 4) * 16;

    const uint32_t* KB0 = g_Kp + (size_t)bh * 2048 * 32;
    const uint32_t* VB0 = g_Vp + (size_t)bh * 64 * 1024;
    // producer mapping: 512 16B chunks per tile, 4 per thread
    const int prow = tid >> 3, pj4 = (tid & 7) * 4;

#define FISSUE(it_) do { \
    const int st_ = (it_) & 1; \
    const uint32_t* KP_ = KB0 + (size_t)(it_) * 64 * 32; \
    const uint32_t* VP_ = VB0 + (it_) * 32; \
    uint32_t* dk_ = SK + st_ * FPL; \
    uint32_t* dv_ = SV + st_ * FPL; \
    _Pragma("unroll") \
    for (int u_ = 0; u_ < 4; u_++) { \
        const int r_ = prow + u_ * 16; \
        CP16(s2u(&dk_[r_ * KSTR + pj4]), &KP_[r_ * 32 + pj4]); \
        CP16(s2u(&dv_[r_ * KSTR + pj4]), &VP_[(size_t)r_ * 1024 + pj4]); \
    } } while(0)

    FISSUE(0); CP_COMMIT;

    for (int kt0 = 0; kt0 < 32; ++kt0) {
        const int kt = kt0 * 64;
        if (kt0 < 31) { FISSUE(kt0 + 1); CP_COMMIT; CP_WAIT1; }
        else CP_WAIT0;
        __syncthreads();
        const uint32_t skb = sk + ((kt0 & 1) * FPL) * 4;
        const uint32_t svb = sv + ((kt0 & 1) * FPL) * 4;

        float s[8][4];
#pragma unroll
        for (int nt = 0; nt < 8; nt++)
#pragma unroll
            for (int i = 0; i < 4; i++) s[nt][i] = 0.f;
#pragma unroll
        for (int c = 0; c < 4; c++) {
#pragma unroll
            for (int p = 0; p < 4; p++) {
                uint32_t kb[4];
                uint32_t ra = skb + (uint32_t)((p * 16 + lrow) * KSTR) * 4 + c * 32 + lseg;
                ldx4(kb, ra);
                mma_f16(s[2*p],   qf[c], kb[0], kb[2]);
                mma_f16(s[2*p+1], qf[c], kb[1], kb[3]);
            }
        }

        if (anymask) {
#pragma unroll
            for (int nt = 0; nt < 8; nt++) {
                const int cc = kt + nt * 8 + lc * 2;
                if (mrow0[cc])     s[nt][0] = -1e30f;
                if (mrow0[cc + 1]) s[nt][1] = -1e30f;
                if (mrow1[cc])     s[nt][2] = -1e30f;
                if (mrow1[cc + 1]) s[nt][3] = -1e30f;
            }
        }

        float tm0 = -1e30f, tm1 = -1e30f;
#pragma unroll
        for (int nt = 0; nt < 8; nt++) {
            tm0 = fmaxf(tm0, fmaxf(s[nt][0], s[nt][1]));
            tm1 = fmaxf(tm1, fmaxf(s[nt][2], s[nt][3]));
        }
        tm0 = fmaxf(tm0, __shfl_xor_sync(0xffffffff, tm0, 1));
        tm0 = fmaxf(tm0, __shfl_xor_sync(0xffffffff, tm0, 2));
        tm1 = fmaxf(tm1, __shfl_xor_sync(0xffffffff, tm1, 1));
        tm1 = fmaxf(tm1, __shfl_xor_sync(0xffffffff, tm1, 2));
        float mn0 = fmaxf(m0, tm0), mn1 = fmaxf(m1, tm1);
        float cr0 = ex2(m0 - mn0), cr1 = ex2(m1 - mn1);
        m0 = mn0; m1 = mn1;
        float ts0 = 0.f, ts1 = 0.f;
#pragma unroll
        for (int nt = 0; nt < 8; nt++) {
            s[nt][0] = ex2(s[nt][0] - mn0);
            s[nt][1] = ex2(s[nt][1] - mn0);
            s[nt][2] = ex2(s[nt][2] - mn1);
            s[nt][3] = ex2(s[nt][3] - mn1);
            ts0 += s[nt][0] + s[nt][1];
            ts1 += s[nt][2] + s[nt][3];
        }
        ts0 += __shfl_xor_sync(0xffffffff, ts0, 1);
        ts0 += __shfl_xor_sync(0xffffffff, ts0, 2);
        ts1 += __shfl_xor_sync(0xffffffff, ts1, 1);
        ts1 += __shfl_xor_sync(0xffffffff, ts1, 2);
        l0 = l0 * cr0 + ts0;
        l1 = l1 * cr1 + ts1;
#pragma unroll
        for (int nt = 0; nt < 8; nt++) {
            o[nt][0] *= cr0; o[nt][1] *= cr0;
            o[nt][2] *= cr1; o[nt][3] *= cr1;
        }

#pragma unroll
        for (int kc = 0; kc < 4; kc++) {
            uint32_t pf[4];
            pf[0] = packh(s[2*kc][0],   s[2*kc][1]);
            pf[1] = packh(s[2*kc][2],   s[2*kc][3]);
            pf[2] = packh(s[2*kc+1][0], s[2*kc+1][1]);
            pf[3] = packh(s[2*kc+1][2], s[2*kc+1][3]);
#pragma unroll
            for (int p = 0; p < 4; p++) {
                uint32_t vb[4];
                uint32_t ra = svb + (uint32_t)((p * 16 + lrow) * KSTR) * 4 + kc * 32 + lseg;
                ldx4(vb, ra);
                mma_f16(o[2*p],   pf, vb[0], vb[2]);
                mma_f16(o[2*p+1], pf, vb[1], vb[3]);
            }
        }
        __syncthreads();
    }

    const float inv0 = 1.f / l0, inv1 = 1.f / l1;
    uint32_t* A0h = g_Ah + ((size_t)b * 2048 + t0 + lr) * 512 + h * 32;
    uint32_t* A0l = g_Al + ((size_t)b * 2048 + t0 + lr) * 512 + h * 32;
#pragma unroll
    for (int nt = 0; nt < 8; nt++) {
        const int j = nt * 4 + lc;
        uint32_t hh, ll;
        split2h(o[nt][0] * inv0, o[nt][1] * inv0, hh, ll);
        A0h[j] = hh; A0l[j] = ll;
        split2h(o[nt][2] * inv1, o[nt][3] * inv1, hh, ll);
        A0h[8 * 512 + j] = hh; A0l[8 * 512 + j] = ll;
    }
}

extern "C" void kernel_launch(void* const* d_in, const int* in_sizes, int n_in,
                              void* d_out, int out_size)
{
    const float* query = (const float*)d_in[0];
    const float* key   = (const float*)d_in[1];
    const float* value = (const float*)d_in[2];
    const unsigned char* mask = (const unsigned char*)d_in[3];
    const float* Wq = (const float*)d_in[4];
    const float* Wk = (const float*)d_in[5];
    const float* Wv = (const float*)d_in[6];
    const float* Wo = (const float*)d_in[7];

    const int SMEM_GEMM = 2 * STW2 * 4;   // 110592 B
    cudaFuncSetAttribute(gemm_qkv,   cudaFuncAttributeMaxDynamicSharedMemorySize, SMEM_GEMM);
    cudaFuncSetAttribute(gemm_oproj, cudaFuncAttributeMaxDynamicSharedMemorySize, SMEM_GEMM);

    zero_flag<<<1, 1>>>();
    mask_scan<<<256, 256>>>((const uint4*)mask, (B_ * T_ * T_) / 16);

    pack_all<<<2048, 256>>>(query, key, value, Wq, Wk, Wv, Wo);

    dim3 gq(24, 32);
    gemm_qkv<<<gq, 256, SMEM_GEMM>>>();

    dim3 gv(32, 32);
    v_pack<<<gv, 128>>>();

    dim3 ga(T_ / 64, B_ * H_);
    flash_attn8<<<ga, 128>>>(mask);

    dim3 go(8, 32);
    gemm_oproj<<<go, 256, SMEM_GEMM>>>((float*)d_out);
}

// round 17
// speedup vs baseline: 2.0592x; 1.0004x over previous
#include <cuda_runtime.h>
#include <cuda_fp16.h>
#include <cstdint>
#include <math.h>

#define B_  2
#define T_  2048
#define D_  1024
#define H_  16
#define DH  64

// ------------------------- scratch globals -------------------------
__device__ uint32_t g_qp[4096*512], g_kp[4096*512];
__device__ uint32_t g_Wqp[1024*512], g_Wkp[1024*512];
__device__ uint32_t g_vh[4096*512], g_vl[4096*512];
__device__ uint32_t g_Wvp[1024*512];
__device__ uint32_t g_Wop[1024*512];
__device__ uint32_t g_Qp[B_*H_*T_*32];
__device__ uint32_t g_Kp[B_*H_*T_*32];
__device__ float    g_V [B_*H_*T_*DH];
__device__ uint32_t g_Vp[(size_t)B_*H_*DH*1024];
__device__ uint32_t g_Ah[(size_t)4096*512], g_Al[(size_t)4096*512];
__device__ int      g_mask_any;

// ------------------------- helpers -------------------------
__device__ __forceinline__ uint32_t packh(float x, float y) {
    uint32_t r; asm("cvt.rn.f16x2.f32 %0, %1, %2;" : "=r"(r) : "f"(y), "f"(x)); return r;
}
__device__ __forceinline__ void split2h(float x, float y, uint32_t& h, uint32_t& l) {
    h = packh(x, y);
    __half2 hv = *reinterpret_cast<__half2*>(&h);
    l = packh(x - __half2float(hv.x), y - __half2float(hv.y));
}
__device__ __forceinline__ void mma_f16(float* d, const uint32_t* a, uint32_t b0, uint32_t b1) {
    asm volatile("mma.sync.aligned.m16n8k16.row.col.f32.f16.f16.f32 "
        "{%0,%1,%2,%3}, {%4,%5,%6,%7}, {%8,%9}, {%0,%1,%2,%3};"
        : "+f"(d[0]), "+f"(d[1]), "+f"(d[2]), "+f"(d[3])
        : "r"(a[0]), "r"(a[1]), "r"(a[2]), "r"(a[3]), "r"(b0), "r"(b1));
}
__device__ __forceinline__ void ldx4(uint32_t* r, uint32_t addr) {
    asm volatile("ldmatrix.sync.aligned.m8n8.x4.shared.b16 {%0,%1,%2,%3}, [%4];"
        : "=r"(r[0]), "=r"(r[1]), "=r"(r[2]), "=r"(r[3]) : "r"(addr));
}
__device__ __forceinline__ float ex2(float x) {
    float y; asm("ex2.approx.f32 %0, %1;" : "=f"(y) : "f"(x)); return y;
}
__device__ __forceinline__ uint32_t s2u(const void* p) {
    return (uint32_t)__cvta_generic_to_shared(p);
}
#define CP16(d, s) asm volatile("cp.async.cg.shared.global [%0], [%1], 16;" :: "r"(d), "l"(s))
#define CP_COMMIT  asm volatile("cp.async.commit_group;" ::: "memory")
#define CP_WAIT1   asm volatile("cp.async.wait_group 1;" ::: "memory")
#define CP_WAIT0   asm volatile("cp.async.wait_group 0;" ::: "memory")

// ------------------------- prep kernels -------------------------
__global__ void zero_flag() { g_mask_any = 0; }
__global__ __launch_bounds__(256) void mask_scan(const uint4* __restrict__ m, int n4)
{
    uint32_t acc = 0;
    for (int i = blockIdx.x * 256 + threadIdx.x; i < n4; i += gridDim.x * 256) {
        uint4 v = m[i];
        acc |= v.x | v.y | v.z | v.w;
    }
    acc |= __shfl_xor_sync(0xffffffff, acc, 16);
    acc |= __shfl_xor_sync(0xffffffff, acc, 8);
    acc |= __shfl_xor_sync(0xffffffff, acc, 4);
    acc |= __shfl_xor_sync(0xffffffff, acc, 2);
    acc |= __shfl_xor_sync(0xffffffff, acc, 1);
    if ((threadIdx.x & 31) == 0 && acc) atomicOr(&g_mask_any, 1);
}

__global__ __launch_bounds__(256) void pack_all(
    const float* q, const float* k, const float* v,
    const float* Wq, const float* Wk, const float* Wv, const float* Wo)
{
    const size_t NI = 4096 * 512, NW = 1024 * 512;
    size_t gid = (size_t)blockIdx.x * 256 + threadIdx.x;
    const size_t stride = (size_t)gridDim.x * 256;
    const size_t total = 3 * NI + 4 * NW;
    for (size_t i = gid; i < total; i += stride) {
        if (i < NI) {
            float2 vv = ((const float2*)q)[i];
            g_qp[i] = packh(vv.x, vv.y);
        } else if (i < 2*NI) {
            size_t off = i - NI;
            float2 vv = ((const float2*)k)[off];
            g_kp[off] = packh(vv.x, vv.y);
        } else if (i < 3*NI) {
            size_t off = i - 2*NI;
            float2 vv = ((const float2*)v)[off];
            uint32_t h, l; split2h(vv.x, vv.y, h, l);
            g_vh[off] = h; g_vl[off] = l;
        } else if (i < 3*NI+NW) {
            size_t off = i - 3*NI;
            float2 vv = ((const float2*)Wq)[off];
            g_Wqp[off] = packh(vv.x, vv.y);
        } else if (i < 3*NI+2*NW) {
            size_t off = i - 3*NI - NW;
            float2 vv = ((const float2*)Wk)[off];
            g_Wkp[off] = packh(vv.x, vv.y);
        } else if (i < 3*NI+3*NW) {
            size_t off = i - 3*NI - 2*NW;
            float2 vv = ((const float2*)Wv)[off];
            g_Wvp[off] = packh(vv.x, vv.y);
        } else {
            size_t off = i - 3*NI - 3*NW;
            float2 vv = ((const float2*)Wo)[off];
            g_Wop[off] = packh(vv.x, vv.y);
        }
    }
}

__global__ __launch_bounds__(128) void v_pack()
{
    __shared__ float tile[64][65];
    const int tid = threadIdx.x;
    const int bh = blockIdx.y, kt = blockIdx.x * 64;
    const float* Vb = g_V + ((size_t)bh * 2048 + kt) * 64;
#pragma unroll
    for (int i = 0; i < 16; i++) {
        int idx = tid + i * 128;
        int r = idx >> 5, dp = idx & 31;
        float2 v = ((const float2*)Vb)[r * 32 + dp];
        tile[r][dp * 2] = v.x; tile[r][dp * 2 + 1] = v.y;
    }
    __syncthreads();
#pragma unroll
    for (int i = 0; i < 16; i++) {
        int idx = tid + i * 128;
        int d = idx >> 5, kp = idx & 31;
        g_Vp[((size_t)bh * 64 + d) * 1024 + (kt >> 1) + kp] =
            packh(tile[2 * kp][d], tile[2 * kp + 1][d]);
    }
}

// ------------------------- GEMM mainloops: K_tile = 64 -------------------------
#define KW   36
#define PLW2 (128 * KW)
#define STWH (2 * PLW2)    // QK stage (A, B) — 3 stages
#define STW2 (3 * PLW2)    // V/O stage (Ah, Al, B) — 2 stages

// fp16 single-term (Q / K projections): 3-stage pipeline, 1 barrier/iter
__device__ __forceinline__ void gemm_mainloop_h(
    const uint32_t* __restrict__ A, const uint32_t* __restrict__ B,
    int bm, int bn, uint32_t* sm, float acc[4][4][4],
    int wm, int wn, int lane, int tid)
{
    const uint32_t* gA = A + (size_t)bm * 512;
    const uint32_t* gB = B + (size_t)bn * 512;

#define HISSUE(it_) do { \
    uint32_t* st_ = sm + ((it_) % 3) * STWH; \
    _Pragma("unroll") \
    for (int u_ = 0; u_ < 4; u_++) { \
        const int idx_ = tid + u_ * 256; \
        const int row_ = idx_ >> 3, j4_ = (idx_ & 7) * 4; \
        const size_t go_ = (size_t)row_ * 512 + (it_) * 32 + j4_; \
        const int so_ = row_ * KW + j4_; \
        CP16(s2u(&st_[so_]),        &gA[go_]); \
        CP16(s2u(&st_[PLW2 + so_]), &gB[go_]); \
    } } while(0)

    const uint32_t smb = s2u(sm);
    const int lrow = (lane & 7) + ((lane >> 3) & 1) * 8;
    const int lseg = (lane >> 4) * 16;

    HISSUE(0); CP_COMMIT;
    HISSUE(1); CP_COMMIT;
    for (int it = 0; it < 16; ++it) {
        if (it < 15) CP_WAIT1; else CP_WAIT0;
        __syncthreads();
        if (it + 2 < 16) { HISSUE(it + 2); CP_COMMIT; }
        const uint32_t stb = smb + ((it % 3) * STWH) * 4;
#pragma unroll
        for (int c = 0; c < 4; ++c) {
            uint32_t af[4][4];
#pragma unroll
            for (int mt = 0; mt < 4; ++mt) {
                uint32_t ra = stb + (uint32_t)((wm + mt * 16 + lrow) * KW) * 4 + c * 32 + lseg;
                ldx4(af[mt], ra);
            }
#pragma unroll
            for (int p = 0; p < 2; ++p) {
                uint32_t bb[4];
                uint32_t rb = stb + (uint32_t)PLW2 * 4
                            + (uint32_t)((wn + p * 16 + lrow) * KW) * 4 + c * 32 + lseg;
                ldx4(bb, rb);
#pragma unroll
                for (int mt = 0; mt < 4; ++mt) {
                    mma_f16(acc[mt][2*p],   af[mt], bb[0], bb[2]);
                    mma_f16(acc[mt][2*p+1], af[mt], bb[1], bb[3]);
                }
            }
        }
    }
#undef HISSUE
}

// fp16 split-A 2-term (V / O projections): 2-stage (smem-limited)
__device__ __forceinline__ void gemm_mainloop_h2(
    const uint32_t* __restrict__ Ah, const uint32_t* __restrict__ Al,
    const uint32_t* __restrict__ B,
    int bm, int bn, uint32_t* sm, float acc[4][4][4],
    int wm, int wn, int lane, int tid)
{
    const uint32_t* gAh = Ah + (size_t)bm * 512;
    const uint32_t* gAl = Al + (size_t)bm * 512;
    const uint32_t* gB  = B  + (size_t)bn * 512;

#define H2ISSUE(it_) do { \
    uint32_t* st_ = sm + ((it_) & 1) * STW2; \
    _Pragma("unroll") \
    for (int u_ = 0; u_ < 4; u_++) { \
        const int idx_ = tid + u_ * 256; \
        const int row_ = idx_ >> 3, j4_ = (idx_ & 7) * 4; \
        const size_t go_ = (size_t)row_ * 512 + (it_) * 32 + j4_; \
        const int so_ = row_ * KW + j4_; \
        CP16(s2u(&st_[so_]),            &gAh[go_]); \
        CP16(s2u(&st_[PLW2 + so_]),     &gAl[go_]); \
        CP16(s2u(&st_[2*PLW2 + so_]),   &gB[go_]); \
    } } while(0)

    const uint32_t smb = s2u(sm);
    const int lrow = (lane & 7) + ((lane >> 3) & 1) * 8;
    const int lseg = (lane >> 4) * 16;

    H2ISSUE(0); CP_COMMIT;
    for (int it = 0; it < 16; ++it) {
        if (it < 15) { H2ISSUE(it + 1); CP_COMMIT; CP_WAIT1; }
        else CP_WAIT0;
        __syncthreads();
        const uint32_t stb = smb + ((it & 1) * STW2) * 4;
#pragma unroll
        for (int c = 0; c < 4; ++c) {
            uint32_t ah[4][4], al[4][4];
#pragma unroll
            for (int mt = 0; mt < 4; ++mt) {
                uint32_t ra = stb + (uint32_t)((wm + mt * 16 + lrow) * KW) * 4 + c * 32 + lseg;
                ldx4(ah[mt], ra);
                ldx4(al[mt], ra + PLW2 * 4);
            }
#pragma unroll
            for (int p = 0; p < 2; ++p) {
                uint32_t bb[4];
                uint32_t rb = stb + (uint32_t)(2 * PLW2) * 4
                            + (uint32_t)((wn + p * 16 + lrow) * KW) * 4 + c * 32 + lseg;
                ldx4(bb, rb);
#pragma unroll
                for (int mt = 0; mt < 4; ++mt) {
                    mma_f16(acc[mt][2*p],   ah[mt], bb[0], bb[2]);
                    mma_f16(acc[mt][2*p+1], ah[mt], bb[1], bb[3]);
                }
#pragma unroll
                for (int mt = 0; mt < 4; ++mt) {
                    mma_f16(acc[mt][2*p],   al[mt], bb[0], bb[2]);
                    mma_f16(acc[mt][2*p+1], al[mt], bb[1], bb[3]);
                }
            }
        }
        __syncthreads();
    }
#undef H2ISSUE
}

// ------------------------- fused QKV projection -------------------------
#define QSCALE 0.18033688f
__global__ __launch_bounds__(256, 2) void gemm_qkv()
{
    extern __shared__ __align__(16) uint32_t smw[];
    const int which = blockIdx.x >> 3;
    const int bn = (blockIdx.x & 7) * 128;
    const int bm = blockIdx.y * 128;

    const int tid = threadIdx.x;
    const int wid = tid >> 5, lane = tid & 31;
    const int wm = (wid & 1) * 64, wn = (wid >> 1) * 32;
    const int lr = lane >> 2, lc = lane & 3;

    float acc[4][4][4];
#pragma unroll
    for (int mt = 0; mt < 4; mt++)
#pragma unroll
        for (int nt = 0; nt < 4; nt++)
#pragma unroll
            for (int i = 0; i < 4; i++) acc[mt][nt][i] = 0.f;

    if (which < 2) {
        const uint32_t* A = which == 0 ? g_qp : g_kp;
        const uint32_t* B = which == 0 ? g_Wqp : g_Wkp;
        gemm_mainloop_h(A, B, bm, bn, smw, acc, wm, wn, lane, tid);
        uint32_t* P = which == 0 ? g_Qp : g_Kp;
        const float sc = which == 0 ? QSCALE : 1.0f;
#pragma unroll
        for (int mt = 0; mt < 4; ++mt)
#pragma unroll
            for (int nt = 0; nt < 4; ++nt) {
                const int row  = bm + wm + mt * 16 + lr;
                const int col0 = bn + wn + nt * 8 + lc * 2;
                const int hh = col0 >> 6, j = (col0 & 63) >> 1;
                const float* d = acc[mt][nt];
                int b = row >> 11, t = row & 2047;
                P[((size_t)(b * 16 + hh) * 2048 + t) * 32 + j] = packh(d[0] * sc, d[1] * sc);
                b = (row + 8) >> 11; t = (row + 8) & 2047;
                P[((size_t)(b * 16 + hh) * 2048 + t) * 32 + j] = packh(d[2] * sc, d[3] * sc);
            }
    } else {
        gemm_mainloop_h2(g_vh, g_vl, g_Wvp, bm, bn, smw, acc, wm, wn, lane, tid);
#pragma unroll
        for (int mt = 0; mt < 4; ++mt)
#pragma unroll
            for (int nt = 0; nt < 4; ++nt) {
                const int row  = bm + wm + mt * 16 + lr;
                const int col0 = bn + wn + nt * 8 + lc * 2;
                const int hh = col0 >> 6, dd = col0 & 63;
                const float* d = acc[mt][nt];
                int b = row >> 11, t = row & 2047;
                *(float2*)(g_V + (((size_t)(b * 16 + hh) * 2048 + t) * 64 + dd)) = make_float2(d[0], d[1]);
                b = (row + 8) >> 11; t = (row + 8) & 2047;
                *(float2*)(g_V + (((size_t)(b * 16 + hh) * 2048 + t) * 64 + dd)) = make_float2(d[2], d[3]);
            }
    }
}

// ------------------------- output projection -------------------------
__global__ __launch_bounds__(256, 2) void gemm_oproj(float* __restrict__ C)
{
    extern __shared__ __align__(16) uint32_t smw[];
    const int bn = blockIdx.x * 128;
    const int bm = blockIdx.y * 128;
    const int tid = threadIdx.x;
    const int wid = tid >> 5, lane = tid & 31;
    const int wm = (wid & 1) * 64, wn = (wid >> 1) * 32;
    const int lr = lane >> 2, lc = lane & 3;

    float acc[4][4][4];
#pragma unroll
    for (int mt = 0; mt < 4; mt++)
#pragma unroll
        for (int nt = 0; nt < 4; nt++)
#pragma unroll
            for (int i = 0; i < 4; i++) acc[mt][nt][i] = 0.f;

    gemm_mainloop_h2(g_Ah, g_Al, g_Wop, bm, bn, smw, acc, wm, wn, lane, tid);

#pragma unroll
    for (int mt = 0; mt < 4; ++mt)
#pragma unroll
        for (int nt = 0; nt < 4; ++nt) {
            const int row  = bm + wm + mt * 16 + lr;
            const int col0 = bn + wn + nt * 8 + lc * 2;
            const float* d = acc[mt][nt];
            *(float2*)(C + (size_t)row * 1024 + col0)       = make_float2(d[0], d[1]);
            *(float2*)(C + (size_t)(row + 8) * 1024 + col0) = make_float2(d[2], d[3]);
        }
}

// ------------------------- flash attention: fp16, 3-stage cp.async -------------------------
#define KSTR 36
#define FPL (64 * KSTR)
__global__ __launch_bounds__(128, 4) void flash_attn9(
    const unsigned char* __restrict__ mask)
{
    __shared__ __align__(16) uint32_t SK[3 * FPL], SV[3 * FPL];

    const int tid = threadIdx.x;
    const int w = tid >> 5, lane = tid & 31;
    const int lr = lane >> 2, lc = lane & 3;
    const int bh = blockIdx.y, b = bh >> 4, h = bh & 15;
    const int q0 = blockIdx.x * 64;
    const int t0 = q0 + w * 16;
    const bool anymask = (g_mask_any != 0);

    uint32_t qf[4][4];
    {
        const uint32_t* q0p = g_Qp + ((size_t)bh * 2048 + t0 + lr) * 32;
        const uint32_t* q1p = q0p + 8 * 32;
#pragma unroll
        for (int c = 0; c < 4; c++) {
            const int j = c * 8 + lc;
            qf[c][0] = q0p[j];     qf[c][1] = q1p[j];
            qf[c][2] = q0p[j + 4]; qf[c][3] = q1p[j + 4];
        }
    }

    float m0 = -1e30f, m1 = -1e30f, l0 = 0.f, l1 = 0.f;
    float o[8][4];
#pragma unroll
    for (int nt = 0; nt < 8; nt++)
#pragma unroll
        for (int i = 0; i < 4; i++) o[nt][i] = 0.f;

    const unsigned char* mrow0 = mask + ((size_t)b * 2048 + t0 + lr) * 2048;
    const unsigned char* mrow1 = mrow0 + 8 * 2048;

    const uint32_t sk = s2u(SK), sv = s2u(SV);
    const int lrow = (lane & 7) + ((lane >> 3) & 1) * 8;
    const int lseg = (lane >> 4) * 16;

    const uint32_t* KB0 = g_Kp + (size_t)bh * 2048 * 32;
    const uint32_t* VB0 = g_Vp + (size_t)bh * 64 * 1024;
    const int prow = tid >> 3, pj4 = (tid & 7) * 4;

#define FISSUE(it_) do { \
    const int st_ = (it_) % 3; \
    const uint32_t* KP_ = KB0 + (size_t)(it_) * 64 * 32; \
    const uint32_t* VP_ = VB0 + (it_) * 32; \
    uint32_t* dk_ = SK + st_ * FPL; \
    uint32_t* dv_ = SV + st_ * FPL; \
    _Pragma("unroll") \
    for (int u_ = 0; u_ < 4; u_++) { \
        const int r_ = prow + u_ * 16; \
        CP16(s2u(&dk_[r_ * KSTR + pj4]), &KP_[r_ * 32 + pj4]); \
        CP16(s2u(&dv_[r_ * KSTR + pj4]), &VP_[(size_t)r_ * 1024 + pj4]); \
    } } while(0)

    FISSUE(0); CP_COMMIT;
    FISSUE(1); CP_COMMIT;

    for (int kt0 = 0; kt0 < 32; ++kt0) {
        const int kt = kt0 * 64;
        if (kt0 < 31) CP_WAIT1; else CP_WAIT0;
        __syncthreads();
        if (kt0 + 2 < 32) { FISSUE(kt0 + 2); CP_COMMIT; }
        const uint32_t skb = sk + ((kt0 % 3) * FPL) * 4;
        const uint32_t svb = sv + ((kt0 % 3) * FPL) * 4;

        float s[8][4];
#pragma unroll
        for (int nt = 0; nt < 8; nt++)
#pragma unroll
            for (int i = 0; i < 4; i++) s[nt][i] = 0.f;
#pragma unroll
        for (int c = 0; c < 4; c++) {
#pragma unroll
            for (int p = 0; p < 4; p++) {
                uint32_t kb[4];
                uint32_t ra = skb + (uint32_t)((p * 16 + lrow) * KSTR) * 4 + c * 32 + lseg;
                ldx4(kb, ra);
                mma_f16(s[2*p],   qf[c], kb[0], kb[2]);
                mma_f16(s[2*p+1], qf[c], kb[1], kb[3]);
            }
        }

        if (anymask) {
#pragma unroll
            for (int nt = 0; nt < 8; nt++) {
                const int cc = kt + nt * 8 + lc * 2;
                if (mrow0[cc])     s[nt][0] = -1e30f;
                if (mrow0[cc + 1]) s[nt][1] = -1e30f;
                if (mrow1[cc])     s[nt][2] = -1e30f;
                if (mrow1[cc + 1]) s[nt][3] = -1e30f;
            }
        }

        float tm0 = -1e30f, tm1 = -1e30f;
#pragma unroll
        for (int nt = 0; nt < 8; nt++) {
            tm0 = fmaxf(tm0, fmaxf(s[nt][0], s[nt][1]));
            tm1 = fmaxf(tm1, fmaxf(s[nt][2], s[nt][3]));
        }
        tm0 = fmaxf(tm0, __shfl_xor_sync(0xffffffff, tm0, 1));
        tm0 = fmaxf(tm0, __shfl_xor_sync(0xffffffff, tm0, 2));
        tm1 = fmaxf(tm1, __shfl_xor_sync(0xffffffff, tm1, 1));
        tm1 = fmaxf(tm1, __shfl_xor_sync(0xffffffff, tm1, 2));
        float mn0 = fmaxf(m0, tm0), mn1 = fmaxf(m1, tm1);
        float cr0 = ex2(m0 - mn0), cr1 = ex2(m1 - mn1);
        m0 = mn0; m1 = mn1;
        float ts0 = 0.f, ts1 = 0.f;
#pragma unroll
        for (int nt = 0; nt < 8; nt++) {
            s[nt][0] = ex2(s[nt][0] - mn0);
            s[nt][1] = ex2(s[nt][1] - mn0);
            s[nt][2] = ex2(s[nt][2] - mn1);
            s[nt][3] = ex2(s[nt][3] - mn1);
            ts0 += s[nt][0] + s[nt][1];
            ts1 += s[nt][2] + s[nt][3];
        }
        ts0 += __shfl_xor_sync(0xffffffff, ts0, 1);
        ts0 += __shfl_xor_sync(0xffffffff, ts0, 2);
        ts1 += __shfl_xor_sync(0xffffffff, ts1, 1);
        ts1 += __shfl_xor_sync(0xffffffff, ts1, 2);
        l0 = l0 * cr0 + ts0;
        l1 = l1 * cr1 + ts1;
#pragma unroll
        for (int nt = 0; nt < 8; nt++) {
            o[nt][0] *= cr0; o[nt][1] *= cr0;
            o[nt][2] *= cr1; o[nt][3] *= cr1;
        }

#pragma unroll
        for (int kc = 0; kc < 4; kc++) {
            uint32_t pf[4];
            pf[0] = packh(s[2*kc][0],   s[2*kc][1]);
            pf[1] = packh(s[2*kc][2],   s[2*kc][3]);
            pf[2] = packh(s[2*kc+1][0], s[2*kc+1][1]);
            pf[3] = packh(s[2*kc+1][2], s[2*kc+1][3]);
#pragma unroll
            for (int p = 0; p < 4; p++) {
                uint32_t vb[4];
                uint32_t ra = svb + (uint32_t)((p * 16 + lrow) * KSTR) * 4 + kc * 32 + lseg;
                ldx4(vb, ra);
                mma_f16(o[2*p],   pf, vb[0], vb[2]);
                mma_f16(o[2*p+1], pf, vb[1], vb[3]);
            }
        }
    }

    const float inv0 = 1.f / l0, inv1 = 1.f / l1;
    uint32_t* A0h = g_Ah + ((size_t)b * 2048 + t0 + lr) * 512 + h * 32;
    uint32_t* A0l = g_Al + ((size_t)b * 2048 + t0 + lr) * 512 + h * 32;
#pragma unroll
    for (int nt = 0; nt < 8; nt++) {
        const int j = nt * 4 + lc;
        uint32_t hh, ll;
        split2h(o[nt][0] * inv0, o[nt][1] * inv0, hh, ll);
        A0h[j] = hh; A0l[j] = ll;
        split2h(o[nt][2] * inv1, o[nt][3] * inv1, hh, ll);
        A0h[8 * 512 + j] = hh; A0l[8 * 512 + j] = ll;
    }
}

extern "C" void kernel_launch(void* const* d_in, const int* in_sizes, int n_in,
                              void* d_out, int out_size)
{
    const float* query = (const float*)d_in[0];
    const float* key   = (const float*)d_in[1];
    const float* value = (const float*)d_in[2];
    const unsigned char* mask = (const unsigned char*)d_in[3];
    const float* Wq = (const float*)d_in[4];
    const float* Wk = (const float*)d_in[5];
    const float* Wv = (const float*)d_in[6];
    const float* Wo = (const float*)d_in[7];

    const int SMEM_GEMM = 2 * STW2 * 4;   // 110592 B (== 3 * STWH * 4)
    cudaFuncSetAttribute(gemm_qkv,   cudaFuncAttributeMaxDynamicSharedMemorySize, SMEM_GEMM);
    cudaFuncSetAttribute(gemm_oproj, cudaFuncAttributeMaxDynamicSharedMemorySize, SMEM_GEMM);

    zero_flag<<<1, 1>>>();
    mask_scan<<<256, 256>>>((const uint4*)mask, (B_ * T_ * T_) / 16);

    pack_all<<<2048, 256>>>(query, key, value, Wq, Wk, Wv, Wo);

    dim3 gq(24, 32);
    gemm_qkv<<<gq, 256, SMEM_GEMM>>>();

    dim3 gv(32, 32);
    v_pack<<<gv, 128>>>();

    dim3 ga(T_ / 64, B_ * H_);
    flash_attn9<<<ga, 128>>>(mask);

    dim3 go(8, 32);
    gemm_oproj<<<go, 256, SMEM_GEMM>>>((float*)d_out);
}